// round 1
// baseline (speedup 1.0000x reference)
#include <cuda_runtime.h>
#include <math.h>

#define B 64
#define S 1024
#define D 768
#define T 4
#define E 8
#define TOPK 2
#define H 3072
#define NH 12
#define HD 64
#define NT 48          // NH*T
#define NTOK 256       // B*T
#define NPAIR 512      // NTOK*TOPK

// ------------------------- scratch (device globals) -------------------------
__device__ __align__(16) float g_qtilde[NT * D];
__device__ float g_qb[NT];
__device__ __align__(16) float g_scores[(size_t)B * NT * S];   // scores -> attn (in place)
__device__ __align__(16) float g_pooled[(size_t)B * NT * D];
__device__ __align__(16) float g_xln[NTOK * D];
__device__ float g_probs[NTOK * E];
__device__ int   g_topi[NTOK * TOPK];
__device__ float g_topw[NTOK * TOPK];
__device__ int   g_ecnt[E];
__device__ int   g_elist[E * NPAIR];
__device__ __align__(16) float g_h[(size_t)NPAIR * H];
__device__ __align__(16) float g_y[(size_t)NPAIR * D];

__device__ __forceinline__ float wred(float v) {
#pragma unroll
    for (int o = 16; o > 0; o >>= 1) v += __shfl_down_sync(0xffffffffu, v, o);
    return v;
}
__device__ __forceinline__ int wredi(int v) {
#pragma unroll
    for (int o = 16; o > 0; o >>= 1) v += __shfl_down_sync(0xffffffffu, v, o);
    return v;
}

// ------------------------- kA: qtilde = (probe@Wq^T + bq) @ Wk --------------
// grid 48 (ht = h*T + t), 256 threads
__global__ __launch_bounds__(256) void kA_qtilde(
    const float* __restrict__ probe, const float* __restrict__ ipw,
    const float* __restrict__ ipb)
{
    int ht = blockIdx.x;
    int h = ht >> 2, t = ht & 3;
    __shared__ float q_s[HD];
    int tid = threadIdx.x, lane = tid & 31, warp = tid >> 5;

    for (int j = warp; j < HD; j += 8) {
        int row = h * HD + j;                  // Wq row
        const float* w = ipw + (size_t)row * D;
        const float* p = probe + t * D;
        float acc = 0.f;
        for (int dd = lane; dd < D; dd += 32) acc += p[dd] * w[dd];
        acc = wred(acc);
        if (lane == 0) q_s[j] = acc + ipb[row];
    }
    __syncthreads();
    if (tid == 0) {
        float qb = 0.f;
        for (int j = 0; j < HD; j++) qb += q_s[j] * ipb[D + h * HD + j];
        g_qb[ht] = qb;
    }
    for (int dd = tid; dd < D; dd += 256) {
        float acc = 0.f;
        const float* wk = ipw + (size_t)(D + h * HD) * D + dd;
#pragma unroll 8
        for (int j = 0; j < HD; j++) acc += q_s[j] * wk[(size_t)j * D];
        g_qtilde[ht * D + dd] = acc;
    }
}

// ------------------------- kB: scores = hidden @ qtilde^T -------------------
// grid (8 s-tiles, 64 b), 256 threads. Tile: 128 s x 48 n, k-chunks of 32.
#define KB_ST 128
#define KB_KC 32
__global__ __launch_bounds__(256) void kB_scores(const float* __restrict__ hidden)
{
    int b = blockIdx.y;
    int s0 = blockIdx.x * KB_ST;
    __shared__ float hs[KB_ST * 33];     // [s][k], pad 33
    __shared__ float qs[KB_KC * NT];     // [k][n]
    int tid = threadIdx.x;
    int tn = tid & 15;                   // 16 groups x 3 n
    int ts = tid >> 4;                   // 16 groups x 8 s
    float acc[8][3];
#pragma unroll
    for (int i = 0; i < 8; i++) { acc[i][0] = 0.f; acc[i][1] = 0.f; acc[i][2] = 0.f; }

    const float* hb = hidden + ((size_t)b * S + s0) * D;
    for (int k0 = 0; k0 < D; k0 += KB_KC) {
        for (int idx = tid; idx < KB_ST * KB_KC / 4; idx += 256) {
            int s = idx >> 3;
            int ko = (idx & 7) << 2;
            float4 v = *(const float4*)(hb + (size_t)s * D + k0 + ko);
            float* dst = &hs[s * 33 + ko];
            dst[0] = v.x; dst[1] = v.y; dst[2] = v.z; dst[3] = v.w;
        }
        for (int idx = tid; idx < NT * KB_KC; idx += 256) {
            int n = idx >> 5, kk = idx & 31;
            qs[kk * NT + n] = g_qtilde[n * D + k0 + kk];
        }
        __syncthreads();
#pragma unroll 4
        for (int kk = 0; kk < KB_KC; kk++) {
            float q0 = qs[kk * NT + tn * 3 + 0];
            float q1 = qs[kk * NT + tn * 3 + 1];
            float q2 = qs[kk * NT + tn * 3 + 2];
#pragma unroll
            for (int i = 0; i < 8; i++) {
                float hv = hs[(ts * 8 + i) * 33 + kk];
                acc[i][0] += hv * q0; acc[i][1] += hv * q1; acc[i][2] += hv * q2;
            }
        }
        __syncthreads();
    }
#pragma unroll
    for (int j = 0; j < 3; j++) {
        int n = tn * 3 + j;
        float qb = g_qb[n];
#pragma unroll
        for (int i = 0; i < 8; i++) {
            int s = s0 + ts * 8 + i;
            g_scores[((size_t)b * NT + n) * S + s] = 0.125f * (acc[i][j] + qb);
        }
    }
}

// ------------------------- kC: softmax rows + head-mean ---------------------
// grid 256 (b*T + t), 256 threads
__global__ __launch_bounds__(256) void kC_softmax(float* __restrict__ out_aw)
{
    int bt = blockIdx.x, b = bt >> 2, t = bt & 3;
    __shared__ float red[256];
    int tid = threadIdx.x;
    float a0 = 0.f, a1 = 0.f, a2 = 0.f, a3 = 0.f;
    for (int h = 0; h < NH; h++) {
        float* row = &g_scores[((size_t)b * NT + h * T + t) * S];
        float4 v = *(float4*)(row + tid * 4);
        float m = fmaxf(fmaxf(v.x, v.y), fmaxf(v.z, v.w));
        red[tid] = m; __syncthreads();
        for (int o = 128; o > 0; o >>= 1) { if (tid < o) red[tid] = fmaxf(red[tid], red[tid + o]); __syncthreads(); }
        m = red[0]; __syncthreads();
        float e0 = __expf(v.x - m), e1 = __expf(v.y - m), e2 = __expf(v.z - m), e3 = __expf(v.w - m);
        red[tid] = e0 + e1 + e2 + e3; __syncthreads();
        for (int o = 128; o > 0; o >>= 1) { if (tid < o) red[tid] += red[tid + o]; __syncthreads(); }
        float inv = 1.f / red[0]; __syncthreads();
        e0 *= inv; e1 *= inv; e2 *= inv; e3 *= inv;
        *(float4*)(row + tid * 4) = make_float4(e0, e1, e2, e3);
        a0 += e0; a1 += e1; a2 += e2; a3 += e3;
    }
    const float inv12 = 1.f / 12.f;
    float* dst = out_aw + (size_t)bt * S + tid * 4;   // not 16B aligned region -> scalar
    dst[0] = a0 * inv12; dst[1] = a1 * inv12; dst[2] = a2 * inv12; dst[3] = a3 * inv12;
}

// ------------------------- kD: pooled = attn @ hidden -----------------------
// grid (6 n-tiles, 64 b), 256 threads. Tile: 48 m x 128 n, k-chunks of 32 over S.
#define KD_NT 128
#define KD_KC 32
__global__ __launch_bounds__(256) void kD_pooled(const float* __restrict__ hidden)
{
    int b = blockIdx.y;
    int n0 = blockIdx.x * KD_NT;
    __shared__ float as_[NT * 33];       // [m][k]
    __shared__ float hsd[KD_KC * 132];   // [k][n], pad 132 (mult of 4)
    int tid = threadIdx.x;
    int tn = tid & 31;                   // x4 n
    int tm = tid >> 5;                   // 8 groups x 6 m
    float acc[6][4];
#pragma unroll
    for (int i = 0; i < 6; i++) { acc[i][0] = acc[i][1] = acc[i][2] = acc[i][3] = 0.f; }

    for (int k0 = 0; k0 < S; k0 += KD_KC) {
        for (int idx = tid; idx < NT * KD_KC; idx += 256) {
            int m = idx >> 5, kk = idx & 31;
            as_[m * 33 + kk] = g_scores[((size_t)b * NT + m) * S + k0 + kk];
        }
        for (int idx = tid; idx < KD_KC * KD_NT / 4; idx += 256) {
            int kk = idx >> 5;
            int no = (idx & 31) << 2;
            float4 v = *(const float4*)(hidden + ((size_t)b * S + k0 + kk) * D + n0 + no);
            *(float4*)&hsd[kk * 132 + no] = v;
        }
        __syncthreads();
#pragma unroll 4
        for (int kk = 0; kk < KD_KC; kk++) {
            float4 hv = *(float4*)&hsd[kk * 132 + tn * 4];
#pragma unroll
            for (int i = 0; i < 6; i++) {
                float a = as_[(tm * 6 + i) * 33 + kk];
                acc[i][0] += a * hv.x; acc[i][1] += a * hv.y;
                acc[i][2] += a * hv.z; acc[i][3] += a * hv.w;
            }
        }
        __syncthreads();
    }
#pragma unroll
    for (int i = 0; i < 6; i++) {
        int m = tm * 6 + i;
        *(float4*)&g_pooled[((size_t)b * NT + m) * D + n0 + tn * 4] =
            make_float4(acc[i][0], acc[i][1], acc[i][2], acc[i][3]);
    }
}

// ------------------------- kE: v-proj, out-proj, LN, gate, top2 -------------
// grid 64 (b), 256 threads (8 warps)
__global__ __launch_bounds__(256) void kE_head(
    const float* __restrict__ ipw, const float* __restrict__ ipb,
    const float* __restrict__ opw, const float* __restrict__ opb,
    const float* __restrict__ lnw, const float* __restrict__ lnb,
    const float* __restrict__ gw, float* __restrict__ out_y)
{
    int b = blockIdx.x;
    __shared__ float pl[T][D];
    __shared__ float ctx[T][D];
    __shared__ float ao[T][D];
    __shared__ float red[256];
    __shared__ float lg[T][E];
    int tid = threadIdx.x, lane = tid & 31, warp = tid >> 5;

    for (int h = 0; h < NH; h++) {
        __syncthreads();
        for (int idx = tid; idx < T * D; idx += 256) {
            int t = idx / D, dd = idx - t * D;
            pl[t][dd] = g_pooled[((size_t)b * NT + h * T + t) * D + dd];
        }
        __syncthreads();
        for (int j = warp; j < HD; j += 8) {
            int row = 2 * D + h * HD + j;     // Wv row
            const float* w = ipw + (size_t)row * D;
            float a0 = 0.f, a1 = 0.f, a2 = 0.f, a3 = 0.f;
            for (int dd = lane; dd < D; dd += 32) {
                float wv = w[dd];
                a0 += wv * pl[0][dd]; a1 += wv * pl[1][dd];
                a2 += wv * pl[2][dd]; a3 += wv * pl[3][dd];
            }
            a0 = wred(a0); a1 = wred(a1); a2 = wred(a2); a3 = wred(a3);
            if (lane == 0) {
                float bias = ipb[row];
                ctx[0][h * HD + j] = a0 + bias; ctx[1][h * HD + j] = a1 + bias;
                ctx[2][h * HD + j] = a2 + bias; ctx[3][h * HD + j] = a3 + bias;
            }
        }
    }
    __syncthreads();
    for (int r = warp; r < D; r += 8) {
        const float* w = opw + (size_t)r * D;
        float a0 = 0.f, a1 = 0.f, a2 = 0.f, a3 = 0.f;
        for (int dd = lane; dd < D; dd += 32) {
            float wv = w[dd];
            a0 += wv * ctx[0][dd]; a1 += wv * ctx[1][dd];
            a2 += wv * ctx[2][dd]; a3 += wv * ctx[3][dd];
        }
        a0 = wred(a0); a1 = wred(a1); a2 = wred(a2); a3 = wred(a3);
        if (lane == 0) {
            float bias = opb[r];
            ao[0][r] = a0 + bias; ao[1][r] = a1 + bias;
            ao[2][r] = a2 + bias; ao[3][r] = a3 + bias;
        }
    }
    __syncthreads();
    for (int idx = tid; idx < T * D; idx += 256) {
        int t = idx / D, dd = idx - t * D;
        out_y[((size_t)(b * T + t)) * D + dd] = ao[t][dd];   // residual
    }
    // LayerNorm (two-pass, matches reference numerics)
    for (int t = 0; t < T; t++) {
        float s1 = 0.f;
        for (int dd = tid; dd < D; dd += 256) s1 += ao[t][dd];
        red[tid] = s1; __syncthreads();
        for (int o = 128; o > 0; o >>= 1) { if (tid < o) red[tid] += red[tid + o]; __syncthreads(); }
        float mu = red[0] * (1.f / 768.f); __syncthreads();
        float s2 = 0.f;
        for (int dd = tid; dd < D; dd += 256) { float v = ao[t][dd] - mu; s2 += v * v; }
        red[tid] = s2; __syncthreads();
        for (int o = 128; o > 0; o >>= 1) { if (tid < o) red[tid] += red[tid + o]; __syncthreads(); }
        float rstd = rsqrtf(red[0] * (1.f / 768.f) + 1e-6f); __syncthreads();
        for (int dd = tid; dd < D; dd += 256) {
            float x = (ao[t][dd] - mu) * rstd * lnw[dd] + lnb[dd];
            pl[t][dd] = x;
            g_xln[((size_t)(b * T + t)) * D + dd] = x;
        }
    }
    __syncthreads();
    // gate logits: warp e handles expert e for all 4 t
    if (warp < E) {
        for (int t = 0; t < T; t++) {
            float acc = 0.f;
            for (int dd = lane; dd < D; dd += 32)
                acc += pl[t][dd] * gw[((size_t)t * D + dd) * E + warp];
            acc = wred(acc);
            if (lane == 0) lg[t][warp] = acc;
        }
    }
    __syncthreads();
    if (tid < T) {
        int t = tid, tok = b * T + t;
        float p[E];
        float mx = lg[t][0];
        for (int e = 1; e < E; e++) mx = fmaxf(mx, lg[t][e]);
        float sum = 0.f;
        for (int e = 0; e < E; e++) { p[e] = __expf(lg[t][e] - mx); sum += p[e]; }
        float inv = 1.f / sum;
        for (int e = 0; e < E; e++) { p[e] *= inv; g_probs[tok * E + e] = p[e]; }
        int i0 = 0;
        for (int e = 1; e < E; e++) if (p[e] > p[i0]) i0 = e;
        int i1 = (i0 == 0) ? 1 : 0;
        for (int e = 0; e < E; e++) if (e != i0 && p[e] > p[i1]) i1 = e;
        float inv2 = 1.f / (p[i0] + p[i1]);
        g_topi[tok * 2] = i0; g_topi[tok * 2 + 1] = i1;
        g_topw[tok * 2] = p[i0] * inv2; g_topw[tok * 2 + 1] = p[i1] * inv2;
    }
}

// ------------------------- kF: routing lists + moe_loss ---------------------
// 1 block, 256 threads. Deterministic (sequential scans).
__global__ __launch_bounds__(256) void kF_route(float* __restrict__ out_loss)
{
    __shared__ int ti[NPAIR];
    __shared__ float imp_s[E];
    __shared__ int disp_s[E];
    int tid = threadIdx.x, lane = tid & 31, warp = tid >> 5;
    for (int i = tid; i < NPAIR; i += 256) ti[i] = g_topi[i];
    __syncthreads();
    if (warp < E) {
        float acc = 0.f;
        for (int tok = lane; tok < NTOK; tok += 32) acc += g_probs[tok * E + warp];
        int cnt = 0;
        for (int p = lane; p < NPAIR; p += 32) cnt += (ti[p] == warp);
        acc = wred(acc); cnt = wredi(cnt);
        if (lane == 0) { imp_s[warp] = acc * (1.f / NTOK); disp_s[warp] = cnt; }
    }
    __syncthreads();
    if (tid == 0) {
        float loss = 0.f;
        for (int e = 0; e < E; e++) loss += imp_s[e] * ((float)disp_s[e] * (1.f / NTOK));
        out_loss[0] = (float)E * loss;
    }
    if (tid < E) {
        int c = 0;
        for (int p = 0; p < NPAIR; p++)
            if (ti[p] == tid) g_elist[tid * NPAIR + (c++)] = p;
        g_ecnt[tid] = c;
    }
}

// ------------------------- kG: fc1 + gelu (grouped per expert) --------------
// grid (24 h-tiles of 128, 8 experts), 256 threads
#define FC_HT 128
#define FC_KC 64
#define FC_TC 32
__global__ __launch_bounds__(256) void kG_fc1(
    const float* __restrict__ w1, const float* __restrict__ b1)
{
    int e = blockIdx.y;
    int h0 = blockIdx.x * FC_HT;
    int nt = g_ecnt[e];
    if (nt == 0) return;
    __shared__ float ws[FC_HT * 65];     // [hh][dd] stride 65 (conflict-free with h interleave 64)
    __shared__ float xs[FC_KC * 33];     // [dd][tok]
    __shared__ int plist[FC_TC];
    int tid = threadIdx.x;
    int hgrp = tid & 63;                 // h = hgrp, hgrp+64
    int tokgrp = tid >> 6;               // 4 groups x 8 tokens

    for (int c0 = 0; c0 < nt; c0 += FC_TC) {
        int ctn = min(FC_TC, nt - c0);
        __syncthreads();
        if (tid < FC_TC) plist[tid] = (tid < ctn) ? g_elist[e * NPAIR + c0 + tid] : -1;
        __syncthreads();
        float acc[2][8];
#pragma unroll
        for (int i = 0; i < 2; i++)
#pragma unroll
            for (int j = 0; j < 8; j++) acc[i][j] = 0.f;

        for (int k0 = 0; k0 < D; k0 += FC_KC) {
            for (int idx = tid; idx < FC_HT * FC_KC / 4; idx += 256) {
                int hh = idx >> 4;
                int doff = (idx & 15) << 2;
                float4 v = *(const float4*)(w1 + ((size_t)e * H + h0 + hh) * D + k0 + doff);
                float* dst = &ws[hh * 65 + doff];
                dst[0] = v.x; dst[1] = v.y; dst[2] = v.z; dst[3] = v.w;
            }
            for (int idx = tid; idx < FC_TC * FC_KC; idx += 256) {
                int tok = idx >> 6, dd = idx & 63;
                int p = plist[tok];
                xs[dd * 33 + tok] = (p >= 0) ? g_xln[(size_t)(p >> 1) * D + k0 + dd] : 0.f;
            }
            __syncthreads();
#pragma unroll 4
            for (int dd = 0; dd < FC_KC; dd++) {
                float w0 = ws[hgrp * 65 + dd];
                float w1v = ws[(hgrp + 64) * 65 + dd];
#pragma unroll
                for (int j = 0; j < 8; j++) {
                    float xv = xs[dd * 33 + tokgrp * 8 + j];
                    acc[0][j] += w0 * xv;
                    acc[1][j] += w1v * xv;
                }
            }
            __syncthreads();
        }
#pragma unroll
        for (int i = 0; i < 2; i++) {
            int hh = hgrp + 64 * i;
            float bias = b1[e * H + h0 + hh];
#pragma unroll
            for (int j = 0; j < 8; j++) {
                int tok = tokgrp * 8 + j;
                if (tok < ctn) {
                    int p = plist[tok];
                    float x = acc[i][j] + bias;
                    float g = 0.5f * x * (1.f + tanhf(0.7978845608028654f * (x + 0.044715f * x * x * x)));
                    g_h[(size_t)p * H + h0 + hh] = g;
                }
            }
        }
    }
}

// ------------------------- kH: fc2 (grouped per expert) ---------------------
// grid (6 d-tiles of 128, 8 experts), 256 threads
__global__ __launch_bounds__(256) void kH_fc2(
    const float* __restrict__ w2, const float* __restrict__ b2)
{
    int e = blockIdx.y;
    int n0 = blockIdx.x * FC_HT;
    int nt = g_ecnt[e];
    if (nt == 0) return;
    __shared__ float ws[FC_HT * 65];
    __shared__ float xs[FC_KC * 33];
    __shared__ int plist[FC_TC];
    int tid = threadIdx.x;
    int hgrp = tid & 63;
    int tokgrp = tid >> 6;

    for (int c0 = 0; c0 < nt; c0 += FC_TC) {
        int ctn = min(FC_TC, nt - c0);
        __syncthreads();
        if (tid < FC_TC) plist[tid] = (tid < ctn) ? g_elist[e * NPAIR + c0 + tid] : -1;
        __syncthreads();
        float acc[2][8];
#pragma unroll
        for (int i = 0; i < 2; i++)
#pragma unroll
            for (int j = 0; j < 8; j++) acc[i][j] = 0.f;

        for (int k0 = 0; k0 < H; k0 += FC_KC) {
            for (int idx = tid; idx < FC_HT * FC_KC / 4; idx += 256) {
                int hh = idx >> 4;
                int doff = (idx & 15) << 2;
                float4 v = *(const float4*)(w2 + ((size_t)e * D + n0 + hh) * H + k0 + doff);
                float* dst = &ws[hh * 65 + doff];
                dst[0] = v.x; dst[1] = v.y; dst[2] = v.z; dst[3] = v.w;
            }
            for (int idx = tid; idx < FC_TC * FC_KC; idx += 256) {
                int tok = idx >> 6, dd = idx & 63;
                int p = plist[tok];
                xs[dd * 33 + tok] = (p >= 0) ? g_h[(size_t)p * H + k0 + dd] : 0.f;
            }
            __syncthreads();
#pragma unroll 4
            for (int dd = 0; dd < FC_KC; dd++) {
                float w0 = ws[hgrp * 65 + dd];
                float w1v = ws[(hgrp + 64) * 65 + dd];
#pragma unroll
                for (int j = 0; j < 8; j++) {
                    float xv = xs[dd * 33 + tokgrp * 8 + j];
                    acc[0][j] += w0 * xv;
                    acc[1][j] += w1v * xv;
                }
            }
            __syncthreads();
        }
#pragma unroll
        for (int i = 0; i < 2; i++) {
            int hh = hgrp + 64 * i;
            float bias = b2[e * D + n0 + hh];
#pragma unroll
            for (int j = 0; j < 8; j++) {
                int tok = tokgrp * 8 + j;
                if (tok < ctn) {
                    int p = plist[tok];
                    g_y[(size_t)p * D + n0 + hh] = acc[i][j] + bias;
                }
            }
        }
    }
}

// ------------------------- kI: combine -------------------------------------
// grid 256 (token), 256 threads
__global__ __launch_bounds__(256) void kI_combine(float* __restrict__ out_y)
{
    int tok = blockIdx.x;
    int tid = threadIdx.x;
    float w0 = g_topw[tok * 2], w1 = g_topw[tok * 2 + 1];
    const float* y0 = &g_y[(size_t)(tok * 2) * D];
    const float* y1 = &g_y[(size_t)(tok * 2 + 1) * D];
    for (int dd = tid; dd < D; dd += 256)
        out_y[(size_t)tok * D + dd] += w0 * y0[dd] + w1 * y1[dd];
}

// ------------------------- launch ------------------------------------------
extern "C" void kernel_launch(void* const* d_in, const int* in_sizes, int n_in,
                              void* d_out, int out_size)
{
    (void)in_sizes; (void)n_in; (void)out_size;
    const float* hidden = (const float*)d_in[0];
    const float* probe  = (const float*)d_in[1];
    const float* ipw    = (const float*)d_in[2];
    const float* ipb    = (const float*)d_in[3];
    const float* opw    = (const float*)d_in[4];
    const float* opb    = (const float*)d_in[5];
    const float* lnw    = (const float*)d_in[6];
    const float* lnb    = (const float*)d_in[7];
    const float* gw     = (const float*)d_in[8];
    const float* w1     = (const float*)d_in[9];
    const float* b1     = (const float*)d_in[10];
    const float* w2     = (const float*)d_in[11];
    const float* b2     = (const float*)d_in[12];
    float* out = (float*)d_out;

    const int OFF_LOSS = B * T * D;        // 196608
    const int OFF_AW   = OFF_LOSS + 1;     // 196609

    kA_qtilde<<<NT, 256>>>(probe, ipw, ipb);
    kB_scores<<<dim3(S / KB_ST, B), 256>>>(hidden);
    kC_softmax<<<NTOK, 256>>>(out + OFF_AW);
    kD_pooled<<<dim3(D / KD_NT, B), 256>>>(hidden);
    kE_head<<<B, 256>>>(ipw, ipb, opw, opb, lnw, lnb, gw, out);
    kF_route<<<1, 256>>>(out + OFF_LOSS);
    kG_fc1<<<dim3(H / FC_HT, E), 256>>>(w1, b1);
    kH_fc2<<<dim3(D / FC_HT, E), 256>>>(w2, b2);
    kI_combine<<<NTOK, 256>>>(out);
}

// round 3
// speedup vs baseline: 1.9112x; 1.9112x over previous
#include <cuda_runtime.h>
#include <math.h>

#define B 64
#define S 1024
#define D 768
#define T 4
#define E 8
#define TOPK 2
#define H 3072
#define NH 12
#define HD 64
#define NT 48          // NH*T
#define NTOK 256       // B*T
#define NPAIR 512      // NTOK*TOPK

// ---------------- packed f32x2 helpers (FFMA2: 2x fp32 throughput) ---------
typedef unsigned long long f32x2;
__device__ __forceinline__ f32x2 dup2(float v) {
    f32x2 r; asm("mov.b64 %0,{%1,%1};" : "=l"(r) : "f"(v)); return r;
}
__device__ __forceinline__ void fma2(f32x2& c, f32x2 a, f32x2 b) {
    asm("fma.rn.f32x2 %0,%1,%2,%0;" : "+l"(c) : "l"(a), "l"(b));
}
__device__ __forceinline__ float2 unpk(f32x2 v) {
    float2 r; asm("mov.b64 {%0,%1},%2;" : "=f"(r.x), "=f"(r.y) : "l"(v)); return r;
}

// ------------------------- scratch (device globals) -------------------------
__device__ __align__(16) float g_qt[D * NT];        // q-tilde TRANSPOSED [d][nt]
__device__ float g_qb[NT];
__device__ __align__(16) float g_scores[(size_t)B * NT * S];
__device__ __align__(16) float g_pooled[(size_t)B * NT * D];
__device__ __align__(16) float g_ctx[NTOK * D];
__device__ __align__(16) float g_ao[NTOK * D];
__device__ __align__(16) float g_xln[NTOK * D];
__device__ float g_probs[NTOK * E];
__device__ int   g_topi[NTOK * TOPK];
__device__ float g_topw[NTOK * TOPK];
__device__ int   g_ecnt[E];
__device__ int   g_elist[E * NPAIR];
__device__ __align__(16) float g_h[(size_t)NPAIR * H];
__device__ __align__(16) float g_y[(size_t)NPAIR * D];

__device__ __forceinline__ float wred(float v) {
#pragma unroll
    for (int o = 16; o > 0; o >>= 1) v += __shfl_down_sync(0xffffffffu, v, o);
    return v;
}
__device__ __forceinline__ int wredi(int v) {
#pragma unroll
    for (int o = 16; o > 0; o >>= 1) v += __shfl_down_sync(0xffffffffu, v, o);
    return v;
}
__device__ __forceinline__ float gelu_tanh(float x) {
    return 0.5f * x * (1.f + tanhf(0.7978845608028654f * (x + 0.044715f * x * x * x)));
}

// ------------------------- kA: qtilde = (probe@Wq^T + bq) @ Wk --------------
__global__ __launch_bounds__(256) void kA_qtilde(
    const float* __restrict__ probe, const float* __restrict__ ipw,
    const float* __restrict__ ipb)
{
    int ht = blockIdx.x;
    int h = ht >> 2, t = ht & 3;
    __shared__ float q_s[HD];
    int tid = threadIdx.x, lane = tid & 31, warp = tid >> 5;

    for (int j = warp; j < HD; j += 8) {
        int row = h * HD + j;
        const float* w = ipw + (size_t)row * D;
        const float* p = probe + t * D;
        float acc = 0.f;
        for (int dd = lane; dd < D; dd += 32) acc += p[dd] * w[dd];
        acc = wred(acc);
        if (lane == 0) q_s[j] = acc + ipb[row];
    }
    __syncthreads();
    if (tid == 0) {
        float qb = 0.f;
        for (int j = 0; j < HD; j++) qb += q_s[j] * ipb[D + h * HD + j];
        g_qb[ht] = qb;
    }
    for (int dd = tid; dd < D; dd += 256) {
        float acc = 0.f;
        const float* wk = ipw + (size_t)(D + h * HD) * D + dd;
#pragma unroll 8
        for (int j = 0; j < HD; j++) acc += q_s[j] * wk[(size_t)j * D];
        g_qt[dd * NT + ht] = acc;          // transposed store
    }
}

// ------------------------- kB: scores = hidden @ qtilde^T -------------------
// grid (4 s-tiles of 256, 64 b), 256 thr. per-thread 8s(4 pairs) x 6n, f32x2.
#define KB_ST 256
#define KB_KC 16
__global__ __launch_bounds__(256, 2) void kB_scores(const float* __restrict__ hidden)
{
    int b = blockIdx.y;
    int s0 = blockIdx.x * KB_ST;
    // [kk][s], row skew (kk&12); rows with skew spill into next row's unused
    // low columns (same-skew groups) and the LAST row spills into the +16 pad.
    __shared__ __align__(16) float hs[KB_KC * 264 + 16];
    __shared__ __align__(16) float qs[KB_KC * NT];   // [kk][n]
    int tid = threadIdx.x;
    int tn = tid & 7;                     // 8 groups x 6 n
    int ts = tid >> 3;                    // 32 groups x 8 s
    f32x2 acc[4][6];
#pragma unroll
    for (int i = 0; i < 4; i++)
#pragma unroll
        for (int j = 0; j < 6; j++) acc[i][j] = 0ull;

    const float* hb = hidden + ((size_t)b * S + s0) * D;
    for (int k0 = 0; k0 < D; k0 += KB_KC) {
#pragma unroll
        for (int r = 0; r < 4; r++) {
            int idx = tid + 256 * r;
            int s = idx >> 2, ko = (idx & 3) << 2;
            float4 v = *(const float4*)(hb + (size_t)s * D + k0 + ko);
            float* base = &hs[ko * 264 + s + ko];     // skew = ko = (ko+e)&12
            base[0] = v.x; base[264] = v.y; base[528] = v.z; base[792] = v.w;
        }
        __syncthreads();   // hs writes (incl. spill) complete before qs overwrites pad region reads
#pragma unroll
        for (int r = 0; r < 3; r++)
            qs[tid + 256 * r] = g_qt[k0 * NT + tid + 256 * r];
        __syncthreads();
#pragma unroll 4
        for (int kk = 0; kk < KB_KC; kk++) {
            const float* hrow = &hs[kk * 264 + (kk & 12)] + ts * 8;
            ulonglong2 hu0 = *(const ulonglong2*)(hrow);
            ulonglong2 hu1 = *(const ulonglong2*)(hrow + 4);
            const float* qrow = &qs[kk * NT + tn * 6];
#pragma unroll
            for (int j = 0; j < 6; j++) {
                f32x2 qd = dup2(qrow[j]);
                fma2(acc[0][j], hu0.x, qd);
                fma2(acc[1][j], hu0.y, qd);
                fma2(acc[2][j], hu1.x, qd);
                fma2(acc[3][j], hu1.y, qd);
            }
        }
        __syncthreads();
    }
#pragma unroll
    for (int j = 0; j < 6; j++) {
        int n = tn * 6 + j;
        float qb = g_qb[n];
        float* row = &g_scores[((size_t)b * NT + n) * S + s0 + ts * 8];
#pragma unroll
        for (int i = 0; i < 4; i++) {
            float2 u = unpk(acc[i][j]);
            u.x = 0.125f * (u.x + qb);
            u.y = 0.125f * (u.y + qb);
            *(float2*)(row + 2 * i) = u;
        }
    }
}

// ------------------------- kC: softmax rows + head-mean ---------------------
__global__ __launch_bounds__(256) void kC_softmax(float* __restrict__ out_aw)
{
    int bt = blockIdx.x, b = bt >> 2, t = bt & 3;
    __shared__ float red[256];
    int tid = threadIdx.x;
    float a0 = 0.f, a1 = 0.f, a2 = 0.f, a3 = 0.f;
    for (int h = 0; h < NH; h++) {
        float* row = &g_scores[((size_t)b * NT + h * T + t) * S];
        float4 v = *(float4*)(row + tid * 4);
        float m = fmaxf(fmaxf(v.x, v.y), fmaxf(v.z, v.w));
        red[tid] = m; __syncthreads();
        for (int o = 128; o > 0; o >>= 1) { if (tid < o) red[tid] = fmaxf(red[tid], red[tid + o]); __syncthreads(); }
        m = red[0]; __syncthreads();
        float e0 = __expf(v.x - m), e1 = __expf(v.y - m), e2 = __expf(v.z - m), e3 = __expf(v.w - m);
        red[tid] = e0 + e1 + e2 + e3; __syncthreads();
        for (int o = 128; o > 0; o >>= 1) { if (tid < o) red[tid] += red[tid + o]; __syncthreads(); }
        float inv = 1.f / red[0]; __syncthreads();
        e0 *= inv; e1 *= inv; e2 *= inv; e3 *= inv;
        *(float4*)(row + tid * 4) = make_float4(e0, e1, e2, e3);
        a0 += e0; a1 += e1; a2 += e2; a3 += e3;
    }
    const float inv12 = 1.f / 12.f;
    float* dst = out_aw + (size_t)bt * S + tid * 4;
    dst[0] = a0 * inv12; dst[1] = a1 * inv12; dst[2] = a2 * inv12; dst[3] = a3 * inv12;
}

// ------------------------- kD: pooled = attn @ hidden -----------------------
// grid (3 n-tiles of 256, 64 b), 256 thr. per-thread 6m x 8n(4 pairs), f32x2.
#define KD_NT 256
#define KD_KC 16
__global__ __launch_bounds__(256, 2) void kD_pooled(const float* __restrict__ hidden)
{
    int b = blockIdx.y;
    int n0 = blockIdx.x * KD_NT;
    __shared__ __align__(16) float as_[NT * 17];        // [m][kk]
    __shared__ __align__(16) float hsd[KD_KC * 260];    // [kk][n]
    int tid = threadIdx.x;
    int tn = tid & 31;                    // n = tn*4 (+128)
    int tm = tid >> 5;                    // 8 groups x 6 m
    f32x2 acc[6][4];
#pragma unroll
    for (int i = 0; i < 6; i++)
#pragma unroll
        for (int j = 0; j < 4; j++) acc[i][j] = 0ull;

    for (int k0 = 0; k0 < S; k0 += KD_KC) {
#pragma unroll
        for (int r = 0; r < 3; r++) {
            int idx = tid + 256 * r;
            int m = idx >> 4, kk = idx & 15;
            as_[m * 17 + kk] = g_scores[((size_t)b * NT + m) * S + k0 + kk];
        }
#pragma unroll
        for (int r = 0; r < 4; r++) {
            int idx = tid + 256 * r;
            int kk = idx >> 6, no = (idx & 63) << 2;
            float4 v = *(const float4*)(hidden + ((size_t)b * S + k0 + kk) * D + n0 + no);
            *(float4*)&hsd[kk * 260 + no] = v;
        }
        __syncthreads();
#pragma unroll 4
        for (int kk = 0; kk < KD_KC; kk++) {
            const float* hrow = &hsd[kk * 260 + tn * 4];
            ulonglong2 h0 = *(const ulonglong2*)(hrow);
            ulonglong2 h1 = *(const ulonglong2*)(hrow + 128);
#pragma unroll
            for (int i = 0; i < 6; i++) {
                f32x2 ad = dup2(as_[(tm * 6 + i) * 17 + kk]);
                fma2(acc[i][0], h0.x, ad);
                fma2(acc[i][1], h0.y, ad);
                fma2(acc[i][2], h1.x, ad);
                fma2(acc[i][3], h1.y, ad);
            }
        }
        __syncthreads();
    }
#pragma unroll
    for (int i = 0; i < 6; i++) {
        int m = tm * 6 + i;
        float* base = &g_pooled[((size_t)b * NT + m) * D + n0];
        float2 u0 = unpk(acc[i][0]), u1 = unpk(acc[i][1]);
        *(float4*)(base + tn * 4) = make_float4(u0.x, u0.y, u1.x, u1.y);
        float2 u2 = unpk(acc[i][2]), u3 = unpk(acc[i][3]);
        *(float4*)(base + 128 + tn * 4) = make_float4(u2.x, u2.y, u3.x, u3.y);
    }
}

// ------------------------- kE1: v-proj, gridded over (h, b) -----------------
__global__ __launch_bounds__(256) void kE1_vproj(
    const float* __restrict__ ipw, const float* __restrict__ ipb)
{
    int h = blockIdx.x, b = blockIdx.y;
    __shared__ float pl[T][D];
    int tid = threadIdx.x, lane = tid & 31, warp = tid >> 5;
    for (int t = 0; t < T; t++)
        for (int dd = tid; dd < D; dd += 256)
            pl[t][dd] = g_pooled[((size_t)b * NT + h * T + t) * D + dd];
    __syncthreads();
    for (int j = warp; j < HD; j += 8) {
        int row = 2 * D + h * HD + j;
        const float* w = ipw + (size_t)row * D;
        float a0 = 0.f, a1 = 0.f, a2 = 0.f, a3 = 0.f;
        for (int dd = lane; dd < D; dd += 32) {
            float wv = w[dd];
            a0 += wv * pl[0][dd]; a1 += wv * pl[1][dd];
            a2 += wv * pl[2][dd]; a3 += wv * pl[3][dd];
        }
        a0 = wred(a0); a1 = wred(a1); a2 = wred(a2); a3 = wred(a3);
        if (lane == 0) {
            float bias = ipb[row];
            g_ctx[((size_t)(b * T + 0)) * D + h * HD + j] = a0 + bias;
            g_ctx[((size_t)(b * T + 1)) * D + h * HD + j] = a1 + bias;
            g_ctx[((size_t)(b * T + 2)) * D + h * HD + j] = a2 + bias;
            g_ctx[((size_t)(b * T + 3)) * D + h * HD + j] = a3 + bias;
        }
    }
}

// ------------------------- kE2: out-proj GEMM + residual --------------------
// grid (6 r-tiles of 128, 8 tok-tiles of 32), 256 thr. per-thread 4tok x 4r.
__global__ __launch_bounds__(256) void kE2_outproj(
    const float* __restrict__ opw, const float* __restrict__ opb,
    float* __restrict__ out_y)
{
    int r0 = blockIdx.x * 128;
    int t0 = blockIdx.y * 32;
    __shared__ __align__(16) float cs[32 * 17];         // [tok][kk]
    __shared__ __align__(16) float ws[16 * 132 + 16];   // [kk][r], skewed by (kk&12)
    int tid = threadIdx.x;
    int tr = tid & 31;                    // r = tr*4
    int tt = tid >> 5;                    // 8 groups x 4 tok
    f32x2 acc[4][2];
#pragma unroll
    for (int t = 0; t < 4; t++) { acc[t][0] = 0ull; acc[t][1] = 0ull; }

    for (int k0 = 0; k0 < D; k0 += 16) {
#pragma unroll
        for (int r = 0; r < 2; r++) {
            int idx = tid + 256 * r;
            int tok = idx >> 4, kk = idx & 15;
            cs[tok * 17 + kk] = g_ctx[(size_t)(t0 + tok) * D + k0 + kk];
        }
#pragma unroll
        for (int r = 0; r < 2; r++) {
            int idx = tid + 256 * r;
            int rr = idx >> 2, ko = (idx & 3) << 2;
            float4 v = *(const float4*)(opw + (size_t)(r0 + rr) * D + k0 + ko);
            float* base = &ws[ko * 132 + rr + ko];
            base[0] = v.x; base[132] = v.y; base[264] = v.z; base[396] = v.w;
        }
        __syncthreads();
#pragma unroll 4
        for (int kk = 0; kk < 16; kk++) {
            ulonglong2 wu = *(const ulonglong2*)(&ws[kk * 132 + (kk & 12)] + tr * 4);
#pragma unroll
            for (int t = 0; t < 4; t++) {
                f32x2 ad = dup2(cs[(tt * 4 + t) * 17 + kk]);
                fma2(acc[t][0], wu.x, ad);
                fma2(acc[t][1], wu.y, ad);
            }
        }
        __syncthreads();
    }
    float4 bb = *(const float4*)&opb[r0 + tr * 4];
#pragma unroll
    for (int t = 0; t < 4; t++) {
        int tok = t0 + tt * 4 + t;
        float2 u0 = unpk(acc[t][0]), u1 = unpk(acc[t][1]);
        float4 o = make_float4(u0.x + bb.x, u0.y + bb.y, u1.x + bb.z, u1.y + bb.w);
        *(float4*)&out_y[(size_t)tok * D + r0 + tr * 4] = o;   // residual
        *(float4*)&g_ao[(size_t)tok * D + r0 + tr * 4] = o;
    }
}

// ------------------------- kE3: LN + gate + top2, per token -----------------
__global__ __launch_bounds__(256) void kE3_ln_gate(
    const float* __restrict__ lnw, const float* __restrict__ lnb,
    const float* __restrict__ gw)
{
    int tok = blockIdx.x;
    int t = tok & 3;
    __shared__ float x[D];
    __shared__ float red[256];
    __shared__ float lg[E];
    int tid = threadIdx.x, lane = tid & 31, warp = tid >> 5;

    float v0 = g_ao[(size_t)tok * D + tid];
    float v1 = g_ao[(size_t)tok * D + tid + 256];
    float v2 = g_ao[(size_t)tok * D + tid + 512];
    red[tid] = v0 + v1 + v2; __syncthreads();
    for (int o = 128; o > 0; o >>= 1) { if (tid < o) red[tid] += red[tid + o]; __syncthreads(); }
    float mu = red[0] * (1.f / 768.f); __syncthreads();
    float d0 = v0 - mu, d1 = v1 - mu, d2 = v2 - mu;
    red[tid] = d0 * d0 + d1 * d1 + d2 * d2; __syncthreads();
    for (int o = 128; o > 0; o >>= 1) { if (tid < o) red[tid] += red[tid + o]; __syncthreads(); }
    float rstd = rsqrtf(red[0] * (1.f / 768.f) + 1e-6f); __syncthreads();

    float x0 = d0 * rstd * lnw[tid] + lnb[tid];
    float x1 = d1 * rstd * lnw[tid + 256] + lnb[tid + 256];
    float x2 = d2 * rstd * lnw[tid + 512] + lnb[tid + 512];
    x[tid] = x0; x[tid + 256] = x1; x[tid + 512] = x2;
    g_xln[(size_t)tok * D + tid] = x0;
    g_xln[(size_t)tok * D + tid + 256] = x1;
    g_xln[(size_t)tok * D + tid + 512] = x2;
    __syncthreads();

    if (warp < E) {
        float acc = 0.f;
        for (int dd = lane; dd < D; dd += 32)
            acc += x[dd] * gw[((size_t)t * D + dd) * E + warp];
        acc = wred(acc);
        if (lane == 0) lg[warp] = acc;
    }
    __syncthreads();
    if (tid == 0) {
        float p[E];
        float mx = lg[0];
        for (int e = 1; e < E; e++) mx = fmaxf(mx, lg[e]);
        float sum = 0.f;
        for (int e = 0; e < E; e++) { p[e] = __expf(lg[e] - mx); sum += p[e]; }
        float inv = 1.f / sum;
        for (int e = 0; e < E; e++) { p[e] *= inv; g_probs[tok * E + e] = p[e]; }
        int i0 = 0;
        for (int e = 1; e < E; e++) if (p[e] > p[i0]) i0 = e;
        int i1 = (i0 == 0) ? 1 : 0;
        for (int e = 0; e < E; e++) if (e != i0 && p[e] > p[i1]) i1 = e;
        float inv2 = 1.f / (p[i0] + p[i1]);
        g_topi[tok * 2] = i0; g_topi[tok * 2 + 1] = i1;
        g_topw[tok * 2] = p[i0] * inv2; g_topw[tok * 2 + 1] = p[i1] * inv2;
    }
}

// ------------------------- kF: routing lists + moe_loss ---------------------
__global__ __launch_bounds__(256) void kF_route(float* __restrict__ out_loss)
{
    __shared__ int ti[NPAIR];
    __shared__ float imp_s[E];
    __shared__ int disp_s[E];
    int tid = threadIdx.x, lane = tid & 31, warp = tid >> 5;
    for (int i = tid; i < NPAIR; i += 256) ti[i] = g_topi[i];
    __syncthreads();
    if (warp < E) {
        float acc = 0.f;
        for (int tok = lane; tok < NTOK; tok += 32) acc += g_probs[tok * E + warp];
        int cnt = 0;
        for (int p = lane; p < NPAIR; p += 32) cnt += (ti[p] == warp);
        acc = wred(acc); cnt = wredi(cnt);
        if (lane == 0) { imp_s[warp] = acc * (1.f / NTOK); disp_s[warp] = cnt; }
    }
    __syncthreads();
    if (tid == 0) {
        float loss = 0.f;
        for (int e = 0; e < E; e++) loss += imp_s[e] * ((float)disp_s[e] * (1.f / NTOK));
        out_loss[0] = (float)E * loss;
    }
    if (tid < E) {
        int c = 0;
        for (int p = 0; p < NPAIR; p++)
            if (ti[p] == tid) g_elist[tid * NPAIR + (c++)] = p;
        g_ecnt[tid] = c;
    }
}

// ------------------------- kG: fc1 + gelu, grid (h-tile, e, chunk) ----------
#define GH_HT 256
#define GH_KC 32
__global__ __launch_bounds__(256) void kG_fc1(
    const float* __restrict__ w1, const float* __restrict__ b1)
{
    int h0 = blockIdx.x * GH_HT;
    int e = blockIdx.y;
    int c0 = blockIdx.z * 32;
    int nt = g_ecnt[e];
    if (c0 >= nt) return;
    int ctn = min(32, nt - c0);
    __shared__ __align__(16) float ws[GH_HT * 33];      // [hh][dd]
    __shared__ __align__(16) float xs[GH_KC * 34];      // [dd][tok]
    __shared__ int plist[32];
    int tid = threadIdx.x;
    int hgrp = tid & 63;
    int tokg = tid >> 6;
    if (tid < 32) plist[tid] = (tid < ctn) ? g_elist[e * NPAIR + c0 + tid] : -1;
    __syncthreads();
    f32x2 acc[4][4];
#pragma unroll
    for (int i = 0; i < 4; i++)
#pragma unroll
        for (int j = 0; j < 4; j++) acc[i][j] = 0ull;

    for (int k0 = 0; k0 < D; k0 += GH_KC) {
#pragma unroll
        for (int r = 0; r < 8; r++) {
            int idx = tid + 256 * r;
            int hh = idx >> 3, doff = (idx & 7) << 2;
            float4 v = *(const float4*)(w1 + ((size_t)e * H + h0 + hh) * D + k0 + doff);
            float* bp = &ws[hh * 33 + doff];
            bp[0] = v.x; bp[1] = v.y; bp[2] = v.z; bp[3] = v.w;
        }
#pragma unroll
        for (int r = 0; r < 4; r++) {
            int idx = tid + 256 * r;
            int tokx = idx & 31, dd = idx >> 5;
            int p = plist[tokx];
            xs[dd * 34 + tokx] = (p >= 0) ? g_xln[(size_t)(p >> 1) * D + k0 + dd] : 0.f;
        }
        __syncthreads();
#pragma unroll 2
        for (int dd = 0; dd < GH_KC; dd++) {
            f32x2 xv0 = *(const f32x2*)&xs[dd * 34 + tokg * 8 + 0];
            f32x2 xv1 = *(const f32x2*)&xs[dd * 34 + tokg * 8 + 2];
            f32x2 xv2 = *(const f32x2*)&xs[dd * 34 + tokg * 8 + 4];
            f32x2 xv3 = *(const f32x2*)&xs[dd * 34 + tokg * 8 + 6];
#pragma unroll
            for (int i = 0; i < 4; i++) {
                f32x2 wd = dup2(ws[(hgrp + 64 * i) * 33 + dd]);
                fma2(acc[i][0], xv0, wd);
                fma2(acc[i][1], xv1, wd);
                fma2(acc[i][2], xv2, wd);
                fma2(acc[i][3], xv3, wd);
            }
        }
        __syncthreads();
    }
#pragma unroll
    for (int i = 0; i < 4; i++) {
        int hh = hgrp + 64 * i;
        float bias = b1[e * H + h0 + hh];
#pragma unroll
        for (int j = 0; j < 4; j++) {
            float2 u = unpk(acc[i][j]);
            int tok = tokg * 8 + 2 * j;
            if (tok < ctn) {
                int p = plist[tok];
                g_h[(size_t)p * H + h0 + hh] = gelu_tanh(u.x + bias);
            }
            if (tok + 1 < ctn) {
                int p = plist[tok + 1];
                g_h[(size_t)p * H + h0 + hh] = gelu_tanh(u.y + bias);
            }
        }
    }
}

// ------------------------- kH: fc2, grid (d-tile, e, chunk) -----------------
__global__ __launch_bounds__(256) void kH_fc2(
    const float* __restrict__ w2, const float* __restrict__ b2)
{
    int n0 = blockIdx.x * GH_HT;
    int e = blockIdx.y;
    int c0 = blockIdx.z * 32;
    int nt = g_ecnt[e];
    if (c0 >= nt) return;
    int ctn = min(32, nt - c0);
    __shared__ __align__(16) float ws[GH_HT * 33];
    __shared__ __align__(16) float xs[GH_KC * 34];
    __shared__ int plist[32];
    int tid = threadIdx.x;
    int hgrp = tid & 63;
    int tokg = tid >> 6;
    if (tid < 32) plist[tid] = (tid < ctn) ? g_elist[e * NPAIR + c0 + tid] : -1;
    __syncthreads();
    f32x2 acc[4][4];
#pragma unroll
    for (int i = 0; i < 4; i++)
#pragma unroll
        for (int j = 0; j < 4; j++) acc[i][j] = 0ull;

    for (int k0 = 0; k0 < H; k0 += GH_KC) {
#pragma unroll
        for (int r = 0; r < 8; r++) {
            int idx = tid + 256 * r;
            int hh = idx >> 3, doff = (idx & 7) << 2;
            float4 v = *(const float4*)(w2 + ((size_t)e * D + n0 + hh) * H + k0 + doff);
            float* bp = &ws[hh * 33 + doff];
            bp[0] = v.x; bp[1] = v.y; bp[2] = v.z; bp[3] = v.w;
        }
#pragma unroll
        for (int r = 0; r < 4; r++) {
            int idx = tid + 256 * r;
            int tokx = idx & 31, dd = idx >> 5;
            int p = plist[tokx];
            xs[dd * 34 + tokx] = (p >= 0) ? g_h[(size_t)p * H + k0 + dd] : 0.f;
        }
        __syncthreads();
#pragma unroll 2
        for (int dd = 0; dd < GH_KC; dd++) {
            f32x2 xv0 = *(const f32x2*)&xs[dd * 34 + tokg * 8 + 0];
            f32x2 xv1 = *(const f32x2*)&xs[dd * 34 + tokg * 8 + 2];
            f32x2 xv2 = *(const f32x2*)&xs[dd * 34 + tokg * 8 + 4];
            f32x2 xv3 = *(const f32x2*)&xs[dd * 34 + tokg * 8 + 6];
#pragma unroll
            for (int i = 0; i < 4; i++) {
                f32x2 wd = dup2(ws[(hgrp + 64 * i) * 33 + dd]);
                fma2(acc[i][0], xv0, wd);
                fma2(acc[i][1], xv1, wd);
                fma2(acc[i][2], xv2, wd);
                fma2(acc[i][3], xv3, wd);
            }
        }
        __syncthreads();
    }
#pragma unroll
    for (int i = 0; i < 4; i++) {
        int hh = hgrp + 64 * i;
        float bias = b2[e * D + n0 + hh];
#pragma unroll
        for (int j = 0; j < 4; j++) {
            float2 u = unpk(acc[i][j]);
            int tok = tokg * 8 + 2 * j;
            if (tok < ctn) {
                int p = plist[tok];
                g_y[(size_t)p * D + n0 + hh] = u.x + bias;
            }
            if (tok + 1 < ctn) {
                int p = plist[tok + 1];
                g_y[(size_t)p * D + n0 + hh] = u.y + bias;
            }
        }
    }
}

// ------------------------- kI: combine -------------------------------------
__global__ __launch_bounds__(256) void kI_combine(float* __restrict__ out_y)
{
    int tok = blockIdx.x;
    int tid = threadIdx.x;
    float w0 = g_topw[tok * 2], w1 = g_topw[tok * 2 + 1];
    const float* y0 = &g_y[(size_t)(tok * 2) * D];
    const float* y1 = &g_y[(size_t)(tok * 2 + 1) * D];
    for (int dd = tid; dd < D; dd += 256)
        out_y[(size_t)tok * D + dd] += w0 * y0[dd] + w1 * y1[dd];
}

// ------------------------- launch ------------------------------------------
extern "C" void kernel_launch(void* const* d_in, const int* in_sizes, int n_in,
                              void* d_out, int out_size)
{
    (void)in_sizes; (void)n_in; (void)out_size;
    const float* hidden = (const float*)d_in[0];
    const float* probe  = (const float*)d_in[1];
    const float* ipw    = (const float*)d_in[2];
    const float* ipb    = (const float*)d_in[3];
    const float* opw    = (const float*)d_in[4];
    const float* opb    = (const float*)d_in[5];
    const float* lnw    = (const float*)d_in[6];
    const float* lnb    = (const float*)d_in[7];
    const float* gw     = (const float*)d_in[8];
    const float* w1     = (const float*)d_in[9];
    const float* b1     = (const float*)d_in[10];
    const float* w2     = (const float*)d_in[11];
    const float* b2     = (const float*)d_in[12];
    float* out = (float*)d_out;

    const int OFF_LOSS = B * T * D;        // 196608
    const int OFF_AW   = OFF_LOSS + 1;     // 196609

    kA_qtilde<<<NT, 256>>>(probe, ipw, ipb);
    kB_scores<<<dim3(S / KB_ST, B), 256>>>(hidden);
    kC_softmax<<<NTOK, 256>>>(out + OFF_AW);
    kD_pooled<<<dim3(D / KD_NT, B), 256>>>(hidden);
    kE1_vproj<<<dim3(NH, B), 256>>>(ipw, ipb);
    kE2_outproj<<<dim3(6, 8), 256>>>(opw, opb, out);
    kE3_ln_gate<<<NTOK, 256>>>(lnw, lnb, gw);
    kF_route<<<1, 256>>>(out + OFF_LOSS);
    kG_fc1<<<dim3(H / GH_HT, E, 16), 256>>>(w1, b1);
    kH_fc2<<<dim3(D / GH_HT, E, 16), 256>>>(w2, b2);
    kI_combine<<<NTOK, 256>>>(out);
}

// round 4
// speedup vs baseline: 2.0073x; 1.0503x over previous
#include <cuda_runtime.h>
#include <math.h>

#define B 64
#define S 1024
#define D 768
#define T 4
#define E 8
#define TOPK 2
#define H 3072
#define NH 12
#define HD 64
#define NT 48          // NH*T
#define NTOK 256       // B*T
#define NPAIR 512      // NTOK*TOPK

// ---------------- packed f32x2 helpers (FFMA2: 2x fp32 throughput) ---------
// K-PACKED accumulation: lanes hold even-k / odd-k partial sums; final = lo+hi.
typedef unsigned long long f32x2;
__device__ __forceinline__ void fma2(f32x2& c, f32x2 a, f32x2 b) {
    asm("fma.rn.f32x2 %0,%1,%2,%0;" : "+l"(c) : "l"(a), "l"(b));
}
__device__ __forceinline__ float2 unpk(f32x2 v) {
    float2 r; asm("mov.b64 {%0,%1},%2;" : "=f"(r.x), "=f"(r.y) : "l"(v)); return r;
}
__device__ __forceinline__ f32x2 dup2(float v) {
    f32x2 r; asm("mov.b64 %0,{%1,%1};" : "=l"(r) : "f"(v)); return r;
}

// ------------------------- scratch (device globals) -------------------------
__device__ __align__(16) float g_qt[NT * D];        // q-tilde [nt][d] (natural)
__device__ float g_qb[NT];
__device__ __align__(16) float g_scores[(size_t)B * NT * S];
__device__ __align__(16) float g_pooled[(size_t)B * NT * D];
__device__ __align__(16) float g_ctx[NTOK * D];
__device__ __align__(16) float g_ao[NTOK * D];
__device__ __align__(16) float g_xln[NTOK * D];
__device__ float g_probs[NTOK * E];
__device__ int   g_topi[NTOK * TOPK];
__device__ float g_topw[NTOK * TOPK];
__device__ int   g_ecnt[E];
__device__ int   g_elist[E * NPAIR];
__device__ __align__(16) float g_h[(size_t)NPAIR * H];
__device__ __align__(16) float g_y[(size_t)NPAIR * D];

__device__ __forceinline__ float wred(float v) {
#pragma unroll
    for (int o = 16; o > 0; o >>= 1) v += __shfl_down_sync(0xffffffffu, v, o);
    return v;
}
__device__ __forceinline__ float wredmax(float v) {
#pragma unroll
    for (int o = 16; o > 0; o >>= 1) v = fmaxf(v, __shfl_down_sync(0xffffffffu, v, o));
    return v;
}
__device__ __forceinline__ int wredi(int v) {
#pragma unroll
    for (int o = 16; o > 0; o >>= 1) v += __shfl_down_sync(0xffffffffu, v, o);
    return v;
}
__device__ __forceinline__ float gelu_tanh(float x) {
    return 0.5f * x * (1.f + tanhf(0.7978845608028654f * (x + 0.044715f * x * x * x)));
}

// ------------------------- kA: qtilde = (probe@Wq^T + bq) @ Wk --------------
__global__ __launch_bounds__(256) void kA_qtilde(
    const float* __restrict__ probe, const float* __restrict__ ipw,
    const float* __restrict__ ipb)
{
    int ht = blockIdx.x;
    int h = ht >> 2, t = ht & 3;
    __shared__ float q_s[HD];
    int tid = threadIdx.x, lane = tid & 31, warp = tid >> 5;

    for (int j = warp; j < HD; j += 8) {
        int row = h * HD + j;
        const float* w = ipw + (size_t)row * D;
        const float* p = probe + t * D;
        float acc = 0.f;
        for (int dd = lane; dd < D; dd += 32) acc += p[dd] * w[dd];
        acc = wred(acc);
        if (lane == 0) q_s[j] = acc + ipb[row];
    }
    __syncthreads();
    if (tid == 0) {
        float qb = 0.f;
        for (int j = 0; j < HD; j++) qb += q_s[j] * ipb[D + h * HD + j];
        g_qb[ht] = qb;
    }
    for (int dd = tid; dd < D; dd += 256) {
        float acc = 0.f;
        const float* wk = ipw + (size_t)(D + h * HD) * D + dd;
#pragma unroll 8
        for (int j = 0; j < HD; j++) acc += q_s[j] * wk[(size_t)j * D];
        g_qt[ht * D + dd] = acc;           // natural layout
    }
}

// ------------------------- kB: scores = hidden @ qtilde^T -------------------
// grid (8 s-tiles of 128, 64 b). per-thread 4s x 6n, K-PACKED f32x2.
#define KB_ST 128
#define KB_KC 16
__global__ __launch_bounds__(256, 3) void kB_scores(const float* __restrict__ hidden)
{
    int b = blockIdx.y;
    int s0 = blockIdx.x * KB_ST;
    __shared__ __align__(16) float hs[KB_ST * 20];   // [s][kk], st 20 (STS.128 ok)
    __shared__ __align__(16) float qs[NT * 18];      // [n][kk], st 18 (conflict-free reads)
    int tid = threadIdx.x;
    int tn = tid & 7;                     // 8 n-groups x 6
    int ts = tid >> 3;                    // 32 s-groups x 4
    f32x2 acc[4][6];
#pragma unroll
    for (int i = 0; i < 4; i++)
#pragma unroll
        for (int j = 0; j < 6; j++) acc[i][j] = 0ull;

    const float* hb = hidden + ((size_t)b * S + s0) * D;
    for (int k0 = 0; k0 < D; k0 += KB_KC) {
#pragma unroll
        for (int r = 0; r < 2; r++) {
            int idx = tid + 256 * r;
            int s = idx >> 2, ko = (idx & 3) << 2;
            float4 v = *(const float4*)(hb + (size_t)s * D + k0 + ko);
            *(float4*)&hs[s * 20 + ko] = v;
        }
        if (tid < 192) {
            int n = tid >> 2, ko = (tid & 3) << 2;
            float4 v = *(const float4*)(g_qt + (size_t)n * D + k0 + ko);
            *(float2*)&qs[n * 18 + ko] = make_float2(v.x, v.y);
            *(float2*)&qs[n * 18 + ko + 2] = make_float2(v.z, v.w);
        }
        __syncthreads();
#pragma unroll
        for (int kp = 0; kp < KB_KC / 2; kp++) {
            f32x2 hv[4], qv[6];
#pragma unroll
            for (int i = 0; i < 4; i++)
                hv[i] = *(const f32x2*)&hs[(ts * 4 + i) * 20 + 2 * kp];
#pragma unroll
            for (int j = 0; j < 6; j++)
                qv[j] = *(const f32x2*)&qs[(tn * 6 + j) * 18 + 2 * kp];
#pragma unroll
            for (int i = 0; i < 4; i++)
#pragma unroll
                for (int j = 0; j < 6; j++)
                    fma2(acc[i][j], hv[i], qv[j]);
        }
        __syncthreads();
    }
#pragma unroll
    for (int j = 0; j < 6; j++) {
        int n = tn * 6 + j;
        float qb = g_qb[n];
        float* row = &g_scores[((size_t)b * NT + n) * S + s0 + ts * 4];
#pragma unroll
        for (int i = 0; i < 4; i++) {
            float2 u = unpk(acc[i][j]);
            row[i] = 0.125f * (u.x + u.y + qb);
        }
    }
}

// ------------------------- kC: softmax (warp-per-head) + head-mean ----------
// grid 256 (b*T+t), 384 threads (12 warps = 12 heads)
__global__ __launch_bounds__(384) void kC_softmax(float* __restrict__ out_aw)
{
    int bt = blockIdx.x, b = bt >> 2, t = bt & 3;
    __shared__ float stage[NH][S];        // 48 KB
    int tid = threadIdx.x, lane = tid & 31, warp = tid >> 5;   // warp = head

    float* row = &g_scores[((size_t)b * NT + warp * T + t) * S];
    float4 v[8];
#pragma unroll
    for (int i = 0; i < 8; i++) v[i] = *(float4*)(row + i * 128 + lane * 4);
    float m = -1e30f;
#pragma unroll
    for (int i = 0; i < 8; i++)
        m = fmaxf(m, fmaxf(fmaxf(v[i].x, v[i].y), fmaxf(v[i].z, v[i].w)));
    m = wredmax(m);
    m = __shfl_sync(0xffffffffu, m, 0);
    float sum = 0.f;
#pragma unroll
    for (int i = 0; i < 8; i++) {
        v[i].x = __expf(v[i].x - m); v[i].y = __expf(v[i].y - m);
        v[i].z = __expf(v[i].z - m); v[i].w = __expf(v[i].w - m);
        sum += v[i].x + v[i].y + v[i].z + v[i].w;
    }
    sum = wred(sum);
    float inv = 1.f / __shfl_sync(0xffffffffu, sum, 0);
#pragma unroll
    for (int i = 0; i < 8; i++) {
        v[i].x *= inv; v[i].y *= inv; v[i].z *= inv; v[i].w *= inv;
        *(float4*)(row + i * 128 + lane * 4) = v[i];
        *(float4*)&stage[warp][i * 128 + lane * 4] = v[i];
    }
    __syncthreads();
    const float inv12 = 1.f / 12.f;
#pragma unroll
    for (int r = 0; r < 3; r++) {
        int s = tid + 384 * r;
        if (s < S) {
            float a = 0.f;
#pragma unroll
            for (int h = 0; h < NH; h++) a += stage[h][s];
            out_aw[(size_t)bt * S + s] = a * inv12;
        }
    }
}

// ------------------------- kD: pooled = attn @ hidden -----------------------
// grid (4 n-tiles of 192, 64 b). per-thread 6m x 6n, K-PACKED f32x2.
#define KD_NT 192
#define KD_KC 16
__global__ __launch_bounds__(256, 2) void kD_pooled(const float* __restrict__ hidden)
{
    int b = blockIdx.y;
    int n0 = blockIdx.x * KD_NT;
    __shared__ __align__(16) float as_[NT * 20];       // [m][kk], st 20
    __shared__ __align__(16) float hsd[KD_NT * 18];    // [n][kk], st 18 (transposed)
    int tid = threadIdx.x;
    int tn = tid & 31;                    // n = tn + 32*j
    int tm = tid >> 5;                    // 8 m-groups x 6
    f32x2 acc[6][6];
#pragma unroll
    for (int i = 0; i < 6; i++)
#pragma unroll
        for (int j = 0; j < 6; j++) acc[i][j] = 0ull;

    for (int k0 = 0; k0 < S; k0 += KD_KC) {
        if (tid < 192) {
            int m = tid >> 2, ko = (tid & 3) << 2;
            float4 v = *(const float4*)(g_scores + ((size_t)b * NT + m) * S + k0 + ko);
            *(float4*)&as_[m * 20 + ko] = v;
        }
#pragma unroll
        for (int r = 0; r < 3; r++) {
            int idx = tid + 256 * r;
            int kk = idx & 15, ng = idx >> 4;          // ng 0..47
            float4 v = *(const float4*)(hidden + ((size_t)b * S + k0 + kk) * D + n0 + ng * 4);
            float* dst = &hsd[(ng * 4) * 18 + kk];     // transpose: scalar stores
            dst[0] = v.x; dst[18] = v.y; dst[36] = v.z; dst[54] = v.w;
        }
        __syncthreads();
#pragma unroll
        for (int kp = 0; kp < KD_KC / 2; kp++) {
            f32x2 av[6], hv[6];
#pragma unroll
            for (int i = 0; i < 6; i++)
                av[i] = *(const f32x2*)&as_[(tm * 6 + i) * 20 + 2 * kp];
#pragma unroll
            for (int j = 0; j < 6; j++)
                hv[j] = *(const f32x2*)&hsd[(tn + 32 * j) * 18 + 2 * kp];
#pragma unroll
            for (int i = 0; i < 6; i++)
#pragma unroll
                for (int j = 0; j < 6; j++)
                    fma2(acc[i][j], av[i], hv[j]);
        }
        __syncthreads();
    }
#pragma unroll
    for (int i = 0; i < 6; i++) {
        int m = tm * 6 + i;
        float* base = &g_pooled[((size_t)b * NT + m) * D + n0];
#pragma unroll
        for (int j = 0; j < 6; j++) {
            float2 u = unpk(acc[i][j]);
            base[tn + 32 * j] = u.x + u.y;
        }
    }
}

// ------------------------- kE1: v-proj, gridded over (h, b) -----------------
__global__ __launch_bounds__(256) void kE1_vproj(
    const float* __restrict__ ipw, const float* __restrict__ ipb)
{
    int h = blockIdx.x, b = blockIdx.y;
    __shared__ float pl[T][D];
    int tid = threadIdx.x, lane = tid & 31, warp = tid >> 5;
    for (int t = 0; t < T; t++)
        for (int dd = tid; dd < D; dd += 256)
            pl[t][dd] = g_pooled[((size_t)b * NT + h * T + t) * D + dd];
    __syncthreads();
    for (int j = warp; j < HD; j += 8) {
        int row = 2 * D + h * HD + j;
        const float* w = ipw + (size_t)row * D;
        float a0 = 0.f, a1 = 0.f, a2 = 0.f, a3 = 0.f;
        for (int dd = lane; dd < D; dd += 32) {
            float wv = w[dd];
            a0 += wv * pl[0][dd]; a1 += wv * pl[1][dd];
            a2 += wv * pl[2][dd]; a3 += wv * pl[3][dd];
        }
        a0 = wred(a0); a1 = wred(a1); a2 = wred(a2); a3 = wred(a3);
        if (lane == 0) {
            float bias = ipb[row];
            g_ctx[((size_t)(b * T + 0)) * D + h * HD + j] = a0 + bias;
            g_ctx[((size_t)(b * T + 1)) * D + h * HD + j] = a1 + bias;
            g_ctx[((size_t)(b * T + 2)) * D + h * HD + j] = a2 + bias;
            g_ctx[((size_t)(b * T + 3)) * D + h * HD + j] = a3 + bias;
        }
    }
}

// ------------------------- kE2: out-proj GEMM + residual --------------------
__global__ __launch_bounds__(256) void kE2_outproj(
    const float* __restrict__ opw, const float* __restrict__ opb,
    float* __restrict__ out_y)
{
    int r0 = blockIdx.x * 128;
    int t0 = blockIdx.y * 32;
    __shared__ __align__(16) float cs[32 * 17];         // [tok][kk]
    __shared__ __align__(16) float ws[16 * 132 + 16];   // [kk][r], skewed by (kk&12)
    int tid = threadIdx.x;
    int tr = tid & 31;
    int tt = tid >> 5;
    f32x2 acc[4][2];
#pragma unroll
    for (int t = 0; t < 4; t++) { acc[t][0] = 0ull; acc[t][1] = 0ull; }

    for (int k0 = 0; k0 < D; k0 += 16) {
#pragma unroll
        for (int r = 0; r < 2; r++) {
            int idx = tid + 256 * r;
            int tok = idx >> 4, kk = idx & 15;
            cs[tok * 17 + kk] = g_ctx[(size_t)(t0 + tok) * D + k0 + kk];
        }
#pragma unroll
        for (int r = 0; r < 2; r++) {
            int idx = tid + 256 * r;
            int rr = idx >> 2, ko = (idx & 3) << 2;
            float4 v = *(const float4*)(opw + (size_t)(r0 + rr) * D + k0 + ko);
            float* base = &ws[ko * 132 + rr + ko];
            base[0] = v.x; base[132] = v.y; base[264] = v.z; base[396] = v.w;
        }
        __syncthreads();
#pragma unroll 4
        for (int kk = 0; kk < 16; kk++) {
            ulonglong2 wu = *(const ulonglong2*)(&ws[kk * 132 + (kk & 12)] + tr * 4);
#pragma unroll
            for (int t = 0; t < 4; t++) {
                f32x2 ad = dup2(cs[(tt * 4 + t) * 17 + kk]);
                fma2(acc[t][0], wu.x, ad);
                fma2(acc[t][1], wu.y, ad);
            }
        }
        __syncthreads();
    }
    float4 bb = *(const float4*)&opb[r0 + tr * 4];
#pragma unroll
    for (int t = 0; t < 4; t++) {
        int tok = t0 + tt * 4 + t;
        float2 u0 = unpk(acc[t][0]), u1 = unpk(acc[t][1]);
        float4 o = make_float4(u0.x + bb.x, u0.y + bb.y, u1.x + bb.z, u1.y + bb.w);
        *(float4*)&out_y[(size_t)tok * D + r0 + tr * 4] = o;
        *(float4*)&g_ao[(size_t)tok * D + r0 + tr * 4] = o;
    }
}

// ------------------------- kE3: LN + gate + top2, per token -----------------
__global__ __launch_bounds__(256) void kE3_ln_gate(
    const float* __restrict__ lnw, const float* __restrict__ lnb,
    const float* __restrict__ gw)
{
    int tok = blockIdx.x;
    int t = tok & 3;
    __shared__ float x[D];
    __shared__ float red[256];
    __shared__ float lg[E];
    int tid = threadIdx.x, lane = tid & 31, warp = tid >> 5;

    float v0 = g_ao[(size_t)tok * D + tid];
    float v1 = g_ao[(size_t)tok * D + tid + 256];
    float v2 = g_ao[(size_t)tok * D + tid + 512];
    red[tid] = v0 + v1 + v2; __syncthreads();
    for (int o = 128; o > 0; o >>= 1) { if (tid < o) red[tid] += red[tid + o]; __syncthreads(); }
    float mu = red[0] * (1.f / 768.f); __syncthreads();
    float d0 = v0 - mu, d1 = v1 - mu, d2 = v2 - mu;
    red[tid] = d0 * d0 + d1 * d1 + d2 * d2; __syncthreads();
    for (int o = 128; o > 0; o >>= 1) { if (tid < o) red[tid] += red[tid + o]; __syncthreads(); }
    float rstd = rsqrtf(red[0] * (1.f / 768.f) + 1e-6f); __syncthreads();

    float x0 = d0 * rstd * lnw[tid] + lnb[tid];
    float x1 = d1 * rstd * lnw[tid + 256] + lnb[tid + 256];
    float x2 = d2 * rstd * lnw[tid + 512] + lnb[tid + 512];
    x[tid] = x0; x[tid + 256] = x1; x[tid + 512] = x2;
    g_xln[(size_t)tok * D + tid] = x0;
    g_xln[(size_t)tok * D + tid + 256] = x1;
    g_xln[(size_t)tok * D + tid + 512] = x2;
    __syncthreads();

    if (warp < E) {
        float acc = 0.f;
        for (int dd = lane; dd < D; dd += 32)
            acc += x[dd] * gw[((size_t)t * D + dd) * E + warp];
        acc = wred(acc);
        if (lane == 0) lg[warp] = acc;
    }
    __syncthreads();
    if (tid == 0) {
        float p[E];
        float mx = lg[0];
        for (int e = 1; e < E; e++) mx = fmaxf(mx, lg[e]);
        float sum = 0.f;
        for (int e = 0; e < E; e++) { p[e] = __expf(lg[e] - mx); sum += p[e]; }
        float inv = 1.f / sum;
        for (int e = 0; e < E; e++) { p[e] *= inv; g_probs[tok * E + e] = p[e]; }
        int i0 = 0;
        for (int e = 1; e < E; e++) if (p[e] > p[i0]) i0 = e;
        int i1 = (i0 == 0) ? 1 : 0;
        for (int e = 0; e < E; e++) if (e != i0 && p[e] > p[i1]) i1 = e;
        float inv2 = 1.f / (p[i0] + p[i1]);
        g_topi[tok * 2] = i0; g_topi[tok * 2 + 1] = i1;
        g_topw[tok * 2] = p[i0] * inv2; g_topw[tok * 2 + 1] = p[i1] * inv2;
    }
}

// ------------------------- kF: routing lists + moe_loss ---------------------
__global__ __launch_bounds__(256) void kF_route(float* __restrict__ out_loss)
{
    __shared__ int ti[NPAIR];
    __shared__ float imp_s[E];
    __shared__ int disp_s[E];
    int tid = threadIdx.x, lane = tid & 31, warp = tid >> 5;
    for (int i = tid; i < NPAIR; i += 256) ti[i] = g_topi[i];
    __syncthreads();
    if (warp < E) {
        float acc = 0.f;
        for (int tok = lane; tok < NTOK; tok += 32) acc += g_probs[tok * E + warp];
        int cnt = 0;
        for (int p = lane; p < NPAIR; p += 32) cnt += (ti[p] == warp);
        acc = wred(acc); cnt = wredi(cnt);
        if (lane == 0) { imp_s[warp] = acc * (1.f / NTOK); disp_s[warp] = cnt; }
    }
    __syncthreads();
    if (tid == 0) {
        float loss = 0.f;
        for (int e = 0; e < E; e++) loss += imp_s[e] * ((float)disp_s[e] * (1.f / NTOK));
        out_loss[0] = (float)E * loss;
    }
    if (tid < E) {
        int c = 0;
        for (int p = 0; p < NPAIR; p++)
            if (ti[p] == tid) g_elist[tid * NPAIR + (c++)] = p;
        g_ecnt[tid] = c;
    }
}

// ------------------------- kG: fc1 + gelu, K-PACKED -------------------------
// grid (H/256, E, 16). per-thread 8h x 4tok. ws[hh][dd], xs[tok][dd] st 34.
#define GH_HT 256
#define GH_KC 32
__global__ __launch_bounds__(256, 2) void kG_fc1(
    const float* __restrict__ w1, const float* __restrict__ b1)
{
    int h0 = blockIdx.x * GH_HT;
    int e = blockIdx.y;
    int c0 = blockIdx.z * 32;
    int nt = g_ecnt[e];
    if (c0 >= nt) return;
    int ctn = min(32, nt - c0);
    __shared__ __align__(16) float ws[GH_HT * 34];
    __shared__ __align__(16) float xs[32 * 34];
    __shared__ int plist[32];
    int tid = threadIdx.x;
    int hg = tid & 31;                    // h = hg + 32*i, i 0..7
    int tg = tid >> 5;                    // tok = tg*4 + j, j 0..3
    if (tid < 32) plist[tid] = (tid < ctn) ? g_elist[e * NPAIR + c0 + tid] : -1;
    __syncthreads();
    f32x2 acc[8][4];
#pragma unroll
    for (int i = 0; i < 8; i++)
#pragma unroll
        for (int j = 0; j < 4; j++) acc[i][j] = 0ull;

    for (int k0 = 0; k0 < D; k0 += GH_KC) {
#pragma unroll
        for (int r = 0; r < 8; r++) {
            int idx = tid + 256 * r;
            int hh = idx >> 3, dof = (idx & 7) << 2;
            float4 v = *(const float4*)(w1 + ((size_t)e * H + h0 + hh) * D + k0 + dof);
            *(float2*)&ws[hh * 34 + dof] = make_float2(v.x, v.y);
            *(float2*)&ws[hh * 34 + dof + 2] = make_float2(v.z, v.w);
        }
        {
            int tok = tid >> 3, dof = (tid & 7) << 2;
            int p = plist[tok];
            float4 v = make_float4(0.f, 0.f, 0.f, 0.f);
            if (p >= 0) v = *(const float4*)(g_xln + (size_t)(p >> 1) * D + k0 + dof);
            *(float2*)&xs[tok * 34 + dof] = make_float2(v.x, v.y);
            *(float2*)&xs[tok * 34 + dof + 2] = make_float2(v.z, v.w);
        }
        __syncthreads();
#pragma unroll
        for (int dp = 0; dp < GH_KC / 2; dp++) {
            f32x2 wv[8], xv[4];
#pragma unroll
            for (int i = 0; i < 8; i++)
                wv[i] = *(const f32x2*)&ws[(hg + 32 * i) * 34 + 2 * dp];
#pragma unroll
            for (int j = 0; j < 4; j++)
                xv[j] = *(const f32x2*)&xs[(tg * 4 + j) * 34 + 2 * dp];
#pragma unroll
            for (int i = 0; i < 8; i++)
#pragma unroll
                for (int j = 0; j < 4; j++)
                    fma2(acc[i][j], wv[i], xv[j]);
        }
        __syncthreads();
    }
#pragma unroll
    for (int i = 0; i < 8; i++) {
        int hh = hg + 32 * i;
        float bias = b1[e * H + h0 + hh];
#pragma unroll
        for (int j = 0; j < 4; j++) {
            int tok = tg * 4 + j;
            if (tok < ctn) {
                int p = plist[tok];
                float2 u = unpk(acc[i][j]);
                g_h[(size_t)p * H + h0 + hh] = gelu_tanh(u.x + u.y + bias);
            }
        }
    }
}

// ------------------------- kH: fc2, K-PACKED ---------------------------------
// grid (D/256, E, 16). per-thread 8d x 4tok.
__global__ __launch_bounds__(256, 2) void kH_fc2(
    const float* __restrict__ w2, const float* __restrict__ b2)
{
    int n0 = blockIdx.x * GH_HT;
    int e = blockIdx.y;
    int c0 = blockIdx.z * 32;
    int nt = g_ecnt[e];
    if (c0 >= nt) return;
    int ctn = min(32, nt - c0);
    __shared__ __align__(16) float ws[GH_HT * 34];
    __shared__ __align__(16) float xs[32 * 34];
    __shared__ int plist[32];
    int tid = threadIdx.x;
    int hg = tid & 31;
    int tg = tid >> 5;
    if (tid < 32) plist[tid] = (tid < ctn) ? g_elist[e * NPAIR + c0 + tid] : -1;
    __syncthreads();
    f32x2 acc[8][4];
#pragma unroll
    for (int i = 0; i < 8; i++)
#pragma unroll
        for (int j = 0; j < 4; j++) acc[i][j] = 0ull;

    for (int k0 = 0; k0 < H; k0 += GH_KC) {
#pragma unroll
        for (int r = 0; r < 8; r++) {
            int idx = tid + 256 * r;
            int hh = idx >> 3, dof = (idx & 7) << 2;
            float4 v = *(const float4*)(w2 + ((size_t)e * D + n0 + hh) * H + k0 + dof);
            *(float2*)&ws[hh * 34 + dof] = make_float2(v.x, v.y);
            *(float2*)&ws[hh * 34 + dof + 2] = make_float2(v.z, v.w);
        }
        {
            int tok = tid >> 3, dof = (tid & 7) << 2;
            int p = plist[tok];
            float4 v = make_float4(0.f, 0.f, 0.f, 0.f);
            if (p >= 0) v = *(const float4*)(g_h + (size_t)p * H + k0 + dof);
            *(float2*)&xs[tok * 34 + dof] = make_float2(v.x, v.y);
            *(float2*)&xs[tok * 34 + dof + 2] = make_float2(v.z, v.w);
        }
        __syncthreads();
#pragma unroll
        for (int dp = 0; dp < GH_KC / 2; dp++) {
            f32x2 wv[8], xv[4];
#pragma unroll
            for (int i = 0; i < 8; i++)
                wv[i] = *(const f32x2*)&ws[(hg + 32 * i) * 34 + 2 * dp];
#pragma unroll
            for (int j = 0; j < 4; j++)
                xv[j] = *(const f32x2*)&xs[(tg * 4 + j) * 34 + 2 * dp];
#pragma unroll
            for (int i = 0; i < 8; i++)
#pragma unroll
                for (int j = 0; j < 4; j++)
                    fma2(acc[i][j], wv[i], xv[j]);
        }
        __syncthreads();
    }
#pragma unroll
    for (int i = 0; i < 8; i++) {
        int hh = hg + 32 * i;
        float bias = b2[e * D + n0 + hh];
#pragma unroll
        for (int j = 0; j < 4; j++) {
            int tok = tg * 4 + j;
            if (tok < ctn) {
                int p = plist[tok];
                float2 u = unpk(acc[i][j]);
                g_y[(size_t)p * D + n0 + hh] = u.x + u.y + bias;
            }
        }
    }
}

// ------------------------- kI: combine -------------------------------------
__global__ __launch_bounds__(256) void kI_combine(float* __restrict__ out_y)
{
    int tok = blockIdx.x;
    int tid = threadIdx.x;
    float w0 = g_topw[tok * 2], w1 = g_topw[tok * 2 + 1];
    const float* y0 = &g_y[(size_t)(tok * 2) * D];
    const float* y1 = &g_y[(size_t)(tok * 2 + 1) * D];
    for (int dd = tid; dd < D; dd += 256)
        out_y[(size_t)tok * D + dd] += w0 * y0[dd] + w1 * y1[dd];
}

// ------------------------- launch ------------------------------------------
extern "C" void kernel_launch(void* const* d_in, const int* in_sizes, int n_in,
                              void* d_out, int out_size)
{
    (void)in_sizes; (void)n_in; (void)out_size;
    const float* hidden = (const float*)d_in[0];
    const float* probe  = (const float*)d_in[1];
    const float* ipw    = (const float*)d_in[2];
    const float* ipb    = (const float*)d_in[3];
    const float* opw    = (const float*)d_in[4];
    const float* opb    = (const float*)d_in[5];
    const float* lnw    = (const float*)d_in[6];
    const float* lnb    = (const float*)d_in[7];
    const float* gw     = (const float*)d_in[8];
    const float* w1     = (const float*)d_in[9];
    const float* b1     = (const float*)d_in[10];
    const float* w2     = (const float*)d_in[11];
    const float* b2     = (const float*)d_in[12];
    float* out = (float*)d_out;

    const int OFF_LOSS = B * T * D;        // 196608
    const int OFF_AW   = OFF_LOSS + 1;     // 196609

    kA_qtilde<<<NT, 256>>>(probe, ipw, ipb);
    kB_scores<<<dim3(S / KB_ST, B), 256>>>(hidden);
    kC_softmax<<<NTOK, 384>>>(out + OFF_AW);
    kD_pooled<<<dim3(D / KD_NT, B), 256>>>(hidden);
    kE1_vproj<<<dim3(NH, B), 256>>>(ipw, ipb);
    kE2_outproj<<<dim3(6, 8), 256>>>(opw, opb, out);
    kE3_ln_gate<<<NTOK, 256>>>(lnw, lnb, gw);
    kF_route<<<1, 256>>>(out + OFF_LOSS);
    kG_fc1<<<dim3(H / GH_HT, E, 16), 256>>>(w1, b1);
    kH_fc2<<<dim3(D / GH_HT, E, 16), 256>>>(w2, b2);
    kI_combine<<<NTOK, 256>>>(out);
}

// round 5
// speedup vs baseline: 2.0410x; 1.0168x over previous
#include <cuda_runtime.h>
#include <math.h>

#define B 64
#define S 1024
#define D 768
#define T 4
#define E 8
#define TOPK 2
#define H 3072
#define NH 12
#define HD 64
#define NT 48          // NH*T
#define NTOK 256       // B*T
#define NPAIR 512      // NTOK*TOPK

// ---------------- packed f32x2 helpers (FFMA2: 2x fp32 throughput) ---------
// K-PACKED accumulation: lanes hold even-k / odd-k partial sums; final = lo+hi.
typedef unsigned long long f32x2;
__device__ __forceinline__ void fma2(f32x2& c, f32x2 a, f32x2 b) {
    asm("fma.rn.f32x2 %0,%1,%2,%0;" : "+l"(c) : "l"(a), "l"(b));
}
__device__ __forceinline__ float2 unpk(f32x2 v) {
    float2 r; asm("mov.b64 {%0,%1},%2;" : "=f"(r.x), "=f"(r.y) : "l"(v)); return r;
}
__device__ __forceinline__ f32x2 dup2(float v) {
    f32x2 r; asm("mov.b64 %0,{%1,%1};" : "=l"(r) : "f"(v)); return r;
}

// ------------------------- scratch (device globals) -------------------------
__device__ __align__(16) float g_qt[NT * D];        // q-tilde [nt][d]
__device__ float g_qb[NT];
__device__ __align__(16) float g_scores[(size_t)B * NT * S];
__device__ __align__(16) float g_pooled[(size_t)B * NT * D];
__device__ __align__(16) float g_ctx[NTOK * D];
__device__ __align__(16) float g_ao[NTOK * D];
__device__ __align__(16) float g_xln[NTOK * D];
__device__ float g_probs[NTOK * E];
__device__ int   g_topi[NTOK * TOPK];
__device__ float g_topw[NTOK * TOPK];
__device__ int   g_ecnt[E];
__device__ int   g_elist[E * NPAIR];
__device__ __align__(16) float g_h[(size_t)NPAIR * H];
__device__ __align__(16) float g_y[(size_t)NPAIR * D];

__device__ __forceinline__ float wred(float v) {
#pragma unroll
    for (int o = 16; o > 0; o >>= 1) v += __shfl_down_sync(0xffffffffu, v, o);
    return v;
}
__device__ __forceinline__ float wredmax(float v) {
#pragma unroll
    for (int o = 16; o > 0; o >>= 1) v = fmaxf(v, __shfl_down_sync(0xffffffffu, v, o));
    return v;
}
__device__ __forceinline__ int wredi(int v) {
#pragma unroll
    for (int o = 16; o > 0; o >>= 1) v += __shfl_down_sync(0xffffffffu, v, o);
    return v;
}
__device__ __forceinline__ float gelu_tanh(float x) {
    return 0.5f * x * (1.f + tanhf(0.7978845608028654f * (x + 0.044715f * x * x * x)));
}

// ------------------------- kA: qtilde = (probe@Wq^T + bq) @ Wk --------------
__global__ __launch_bounds__(256) void kA_qtilde(
    const float* __restrict__ probe, const float* __restrict__ ipw,
    const float* __restrict__ ipb)
{
    int ht = blockIdx.x;
    int h = ht >> 2, t = ht & 3;
    __shared__ float q_s[HD];
    int tid = threadIdx.x, lane = tid & 31, warp = tid >> 5;

    for (int j = warp; j < HD; j += 8) {
        int row = h * HD + j;
        const float* w = ipw + (size_t)row * D;
        const float* p = probe + t * D;
        float acc = 0.f;
        for (int dd = lane; dd < D; dd += 32) acc += p[dd] * w[dd];
        acc = wred(acc);
        if (lane == 0) q_s[j] = acc + ipb[row];
    }
    __syncthreads();
    if (tid == 0) {
        float qb = 0.f;
        for (int j = 0; j < HD; j++) qb += q_s[j] * ipb[D + h * HD + j];
        g_qb[ht] = qb;
    }
    for (int dd = tid; dd < D; dd += 256) {
        float acc = 0.f;
        const float* wk = ipw + (size_t)(D + h * HD) * D + dd;
#pragma unroll 8
        for (int j = 0; j < HD; j++) acc += q_s[j] * wk[(size_t)j * D];
        g_qt[ht * D + dd] = acc;
    }
}

// ------------------------- kB: scores = hidden @ qtilde^T -------------------
// grid (8 s-tiles of 128, 64 b). 4s x 6n K-PACKED, register-prefetch pipeline.
#define KB_ST 128
#define KB_KC 16
__global__ __launch_bounds__(256, 2) void kB_scores(const float* __restrict__ hidden)
{
    int b = blockIdx.y;
    int s0 = blockIdx.x * KB_ST;
    __shared__ __align__(16) float hs[KB_ST * 20];   // [s][kk]
    __shared__ __align__(16) float qs[NT * 18];      // [n][kk]
    int tid = threadIdx.x;
    int tn = tid & 7;
    int ts = tid >> 3;
    f32x2 acc[4][6];
#pragma unroll
    for (int i = 0; i < 4; i++)
#pragma unroll
        for (int j = 0; j < 6; j++) acc[i][j] = 0ull;

    const float* hb = hidden + ((size_t)b * S + s0) * D;
    int sA = tid >> 2, koA = (tid & 3) << 2;
    const float* hA = hb + (size_t)sA * D + koA;
    const float* hB = hb + (size_t)(sA + 64) * D + koA;
    const float* qp = g_qt + (size_t)(tid >> 2) * D + ((tid & 3) << 2);

    float4 ph0 = *(const float4*)hA;
    float4 ph1 = *(const float4*)hB;
    float4 pq = make_float4(0.f, 0.f, 0.f, 0.f);
    if (tid < 192) pq = *(const float4*)qp;

    for (int k0 = 0; k0 < D; k0 += KB_KC) {
        *(float4*)&hs[sA * 20 + koA] = ph0;
        *(float4*)&hs[(sA + 64) * 20 + koA] = ph1;
        if (tid < 192) {
            int qn = tid >> 2, qko = (tid & 3) << 2;
            *(float2*)&qs[qn * 18 + qko] = make_float2(pq.x, pq.y);
            *(float2*)&qs[qn * 18 + qko + 2] = make_float2(pq.z, pq.w);
        }
        __syncthreads();
        int k1 = k0 + KB_KC;
        if (k1 < D) {
            ph0 = *(const float4*)(hA + k1);
            ph1 = *(const float4*)(hB + k1);
            if (tid < 192) pq = *(const float4*)(qp + k1);
        }
#pragma unroll
        for (int kp = 0; kp < KB_KC / 2; kp++) {
            f32x2 hv[4], qv[6];
#pragma unroll
            for (int i = 0; i < 4; i++)
                hv[i] = *(const f32x2*)&hs[(ts * 4 + i) * 20 + 2 * kp];
#pragma unroll
            for (int j = 0; j < 6; j++)
                qv[j] = *(const f32x2*)&qs[(tn * 6 + j) * 18 + 2 * kp];
#pragma unroll
            for (int i = 0; i < 4; i++)
#pragma unroll
                for (int j = 0; j < 6; j++)
                    fma2(acc[i][j], hv[i], qv[j]);
        }
        __syncthreads();
    }
#pragma unroll
    for (int j = 0; j < 6; j++) {
        int n = tn * 6 + j;
        float qb = g_qb[n];
        float* row = &g_scores[((size_t)b * NT + n) * S + s0 + ts * 4];
#pragma unroll
        for (int i = 0; i < 4; i++) {
            float2 u = unpk(acc[i][j]);
            row[i] = 0.125f * (u.x + u.y + qb);
        }
    }
}

// ------------------------- kC: softmax (warp-per-head) + head-mean ----------
__global__ __launch_bounds__(384) void kC_softmax(float* __restrict__ out_aw)
{
    int bt = blockIdx.x, b = bt >> 2, t = bt & 3;
    __shared__ float stage[NH][S];
    int tid = threadIdx.x, lane = tid & 31, warp = tid >> 5;

    float* row = &g_scores[((size_t)b * NT + warp * T + t) * S];
    float4 v[8];
#pragma unroll
    for (int i = 0; i < 8; i++) v[i] = *(float4*)(row + i * 128 + lane * 4);
    float m = -1e30f;
#pragma unroll
    for (int i = 0; i < 8; i++)
        m = fmaxf(m, fmaxf(fmaxf(v[i].x, v[i].y), fmaxf(v[i].z, v[i].w)));
    m = wredmax(m);
    m = __shfl_sync(0xffffffffu, m, 0);
    float sum = 0.f;
#pragma unroll
    for (int i = 0; i < 8; i++) {
        v[i].x = __expf(v[i].x - m); v[i].y = __expf(v[i].y - m);
        v[i].z = __expf(v[i].z - m); v[i].w = __expf(v[i].w - m);
        sum += v[i].x + v[i].y + v[i].z + v[i].w;
    }
    sum = wred(sum);
    float inv = 1.f / __shfl_sync(0xffffffffu, sum, 0);
#pragma unroll
    for (int i = 0; i < 8; i++) {
        v[i].x *= inv; v[i].y *= inv; v[i].z *= inv; v[i].w *= inv;
        *(float4*)(row + i * 128 + lane * 4) = v[i];
        *(float4*)&stage[warp][i * 128 + lane * 4] = v[i];
    }
    __syncthreads();
    const float inv12 = 1.f / 12.f;
#pragma unroll
    for (int r = 0; r < 3; r++) {
        int s = tid + 384 * r;
        if (s < S) {
            float a = 0.f;
#pragma unroll
            for (int h = 0; h < NH; h++) a += stage[h][s];
            out_aw[(size_t)bt * S + s] = a * inv12;
        }
    }
}

// ------------------------- kD: pooled = attn @ hidden -----------------------
// grid (4 n-tiles of 192, 64 b). 6m x 6n K-PACKED, register-prefetch pipeline.
#define KD_NT 192
#define KD_KC 16
__global__ __launch_bounds__(256, 2) void kD_pooled(const float* __restrict__ hidden)
{
    int b = blockIdx.y;
    int n0 = blockIdx.x * KD_NT;
    __shared__ __align__(16) float as_[NT * 20];       // [m][kk]
    __shared__ __align__(16) float hsd[KD_NT * 18];    // [n][kk] (transposed)
    int tid = threadIdx.x;
    int tn = tid & 31;
    int tm = tid >> 5;
    f32x2 acc[6][6];
#pragma unroll
    for (int i = 0; i < 6; i++)
#pragma unroll
        for (int j = 0; j < 6; j++) acc[i][j] = 0ull;

    int pm = tid >> 2, pko = (tid & 3) << 2;    // scores loader (tid<192)
    int kkh = tid & 15, ng0 = tid >> 4;          // hidden loader
    const float* sc_base = g_scores + ((size_t)b * NT + (pm < NT ? pm : 0)) * S + pko;
    const float* h_base = hidden + ((size_t)b * S + kkh) * D + n0 + ng0 * 4;

    float4 pa = make_float4(0.f, 0.f, 0.f, 0.f);
    float4 phv[3];
    if (tid < 192) pa = *(const float4*)sc_base;
#pragma unroll
    for (int r = 0; r < 3; r++) phv[r] = *(const float4*)(h_base + 64 * r);

    for (int k0 = 0; k0 < S; k0 += KD_KC) {
        if (tid < 192) *(float4*)&as_[pm * 20 + pko] = pa;
#pragma unroll
        for (int r = 0; r < 3; r++) {
            float* dst = &hsd[((ng0 + 16 * r) * 4) * 18 + kkh];
            dst[0] = phv[r].x; dst[18] = phv[r].y; dst[36] = phv[r].z; dst[54] = phv[r].w;
        }
        __syncthreads();
        int k1 = k0 + KD_KC;
        if (k1 < S) {
            if (tid < 192) pa = *(const float4*)(sc_base + k1);
#pragma unroll
            for (int r = 0; r < 3; r++)
                phv[r] = *(const float4*)(h_base + (size_t)k1 * D + 64 * r);
        }
#pragma unroll
        for (int kp = 0; kp < KD_KC / 2; kp++) {
            f32x2 av[6], hv[6];
#pragma unroll
            for (int i = 0; i < 6; i++)
                av[i] = *(const f32x2*)&as_[(tm * 6 + i) * 20 + 2 * kp];
#pragma unroll
            for (int j = 0; j < 6; j++)
                hv[j] = *(const f32x2*)&hsd[(tn + 32 * j) * 18 + 2 * kp];
#pragma unroll
            for (int i = 0; i < 6; i++)
#pragma unroll
                for (int j = 0; j < 6; j++)
                    fma2(acc[i][j], av[i], hv[j]);
        }
        __syncthreads();
    }
#pragma unroll
    for (int i = 0; i < 6; i++) {
        int m = tm * 6 + i;
        float* base = &g_pooled[((size_t)b * NT + m) * D + n0];
#pragma unroll
        for (int j = 0; j < 6; j++) {
            float2 u = unpk(acc[i][j]);
            base[tn + 32 * j] = u.x + u.y;
        }
    }
}

// ------------------------- kE1: v-proj, gridded over (h, b) -----------------
__global__ __launch_bounds__(256) void kE1_vproj(
    const float* __restrict__ ipw, const float* __restrict__ ipb)
{
    int h = blockIdx.x, b = blockIdx.y;
    __shared__ float pl[T][D];
    int tid = threadIdx.x, lane = tid & 31, warp = tid >> 5;
    for (int t = 0; t < T; t++)
        for (int dd = tid; dd < D; dd += 256)
            pl[t][dd] = g_pooled[((size_t)b * NT + h * T + t) * D + dd];
    __syncthreads();
    for (int j = warp; j < HD; j += 8) {
        int row = 2 * D + h * HD + j;
        const float* w = ipw + (size_t)row * D;
        float a0 = 0.f, a1 = 0.f, a2 = 0.f, a3 = 0.f;
        for (int dd = lane; dd < D; dd += 32) {
            float wv = w[dd];
            a0 += wv * pl[0][dd]; a1 += wv * pl[1][dd];
            a2 += wv * pl[2][dd]; a3 += wv * pl[3][dd];
        }
        a0 = wred(a0); a1 = wred(a1); a2 = wred(a2); a3 = wred(a3);
        if (lane == 0) {
            float bias = ipb[row];
            g_ctx[((size_t)(b * T + 0)) * D + h * HD + j] = a0 + bias;
            g_ctx[((size_t)(b * T + 1)) * D + h * HD + j] = a1 + bias;
            g_ctx[((size_t)(b * T + 2)) * D + h * HD + j] = a2 + bias;
            g_ctx[((size_t)(b * T + 3)) * D + h * HD + j] = a3 + bias;
        }
    }
}

// ------------------------- kE2: out-proj GEMM + residual --------------------
__global__ __launch_bounds__(256) void kE2_outproj(
    const float* __restrict__ opw, const float* __restrict__ opb,
    float* __restrict__ out_y)
{
    int r0 = blockIdx.x * 128;
    int t0 = blockIdx.y * 32;
    __shared__ __align__(16) float cs[32 * 17];
    __shared__ __align__(16) float ws[16 * 132 + 16];
    int tid = threadIdx.x;
    int tr = tid & 31;
    int tt = tid >> 5;
    f32x2 acc[4][2];
#pragma unroll
    for (int t = 0; t < 4; t++) { acc[t][0] = 0ull; acc[t][1] = 0ull; }

    for (int k0 = 0; k0 < D; k0 += 16) {
#pragma unroll
        for (int r = 0; r < 2; r++) {
            int idx = tid + 256 * r;
            int tok = idx >> 4, kk = idx & 15;
            cs[tok * 17 + kk] = g_ctx[(size_t)(t0 + tok) * D + k0 + kk];
        }
#pragma unroll
        for (int r = 0; r < 2; r++) {
            int idx = tid + 256 * r;
            int rr = idx >> 2, ko = (idx & 3) << 2;
            float4 v = *(const float4*)(opw + (size_t)(r0 + rr) * D + k0 + ko);
            float* base = &ws[ko * 132 + rr + ko];
            base[0] = v.x; base[132] = v.y; base[264] = v.z; base[396] = v.w;
        }
        __syncthreads();
#pragma unroll 4
        for (int kk = 0; kk < 16; kk++) {
            ulonglong2 wu = *(const ulonglong2*)(&ws[kk * 132 + (kk & 12)] + tr * 4);
#pragma unroll
            for (int t = 0; t < 4; t++) {
                f32x2 ad = dup2(cs[(tt * 4 + t) * 17 + kk]);
                fma2(acc[t][0], wu.x, ad);
                fma2(acc[t][1], wu.y, ad);
            }
        }
        __syncthreads();
    }
    float4 bb = *(const float4*)&opb[r0 + tr * 4];
#pragma unroll
    for (int t = 0; t < 4; t++) {
        int tok = t0 + tt * 4 + t;
        float2 u0 = unpk(acc[t][0]), u1 = unpk(acc[t][1]);
        float4 o = make_float4(u0.x + bb.x, u0.y + bb.y, u1.x + bb.z, u1.y + bb.w);
        *(float4*)&out_y[(size_t)tok * D + r0 + tr * 4] = o;
        *(float4*)&g_ao[(size_t)tok * D + r0 + tr * 4] = o;
    }
}

// ------------------------- kE3: LN + gate + top2, per token -----------------
__global__ __launch_bounds__(256) void kE3_ln_gate(
    const float* __restrict__ lnw, const float* __restrict__ lnb,
    const float* __restrict__ gw)
{
    int tok = blockIdx.x;
    int t = tok & 3;
    __shared__ float x[D];
    __shared__ float red[256];
    __shared__ float lg[E];
    int tid = threadIdx.x, lane = tid & 31, warp = tid >> 5;

    float v0 = g_ao[(size_t)tok * D + tid];
    float v1 = g_ao[(size_t)tok * D + tid + 256];
    float v2 = g_ao[(size_t)tok * D + tid + 512];
    red[tid] = v0 + v1 + v2; __syncthreads();
    for (int o = 128; o > 0; o >>= 1) { if (tid < o) red[tid] += red[tid + o]; __syncthreads(); }
    float mu = red[0] * (1.f / 768.f); __syncthreads();
    float d0 = v0 - mu, d1 = v1 - mu, d2 = v2 - mu;
    red[tid] = d0 * d0 + d1 * d1 + d2 * d2; __syncthreads();
    for (int o = 128; o > 0; o >>= 1) { if (tid < o) red[tid] += red[tid + o]; __syncthreads(); }
    float rstd = rsqrtf(red[0] * (1.f / 768.f) + 1e-6f); __syncthreads();

    float x0 = d0 * rstd * lnw[tid] + lnb[tid];
    float x1 = d1 * rstd * lnw[tid + 256] + lnb[tid + 256];
    float x2 = d2 * rstd * lnw[tid + 512] + lnb[tid + 512];
    x[tid] = x0; x[tid + 256] = x1; x[tid + 512] = x2;
    g_xln[(size_t)tok * D + tid] = x0;
    g_xln[(size_t)tok * D + tid + 256] = x1;
    g_xln[(size_t)tok * D + tid + 512] = x2;
    __syncthreads();

    if (warp < E) {
        float acc = 0.f;
        for (int dd = lane; dd < D; dd += 32)
            acc += x[dd] * gw[((size_t)t * D + dd) * E + warp];
        acc = wred(acc);
        if (lane == 0) lg[warp] = acc;
    }
    __syncthreads();
    if (tid == 0) {
        float p[E];
        float mx = lg[0];
        for (int e = 1; e < E; e++) mx = fmaxf(mx, lg[e]);
        float sum = 0.f;
        for (int e = 0; e < E; e++) { p[e] = __expf(lg[e] - mx); sum += p[e]; }
        float inv = 1.f / sum;
        for (int e = 0; e < E; e++) { p[e] *= inv; g_probs[tok * E + e] = p[e]; }
        int i0 = 0;
        for (int e = 1; e < E; e++) if (p[e] > p[i0]) i0 = e;
        int i1 = (i0 == 0) ? 1 : 0;
        for (int e = 0; e < E; e++) if (e != i0 && p[e] > p[i1]) i1 = e;
        float inv2 = 1.f / (p[i0] + p[i1]);
        g_topi[tok * 2] = i0; g_topi[tok * 2 + 1] = i1;
        g_topw[tok * 2] = p[i0] * inv2; g_topw[tok * 2 + 1] = p[i1] * inv2;
    }
}

// ------------------------- kF: routing lists + moe_loss ---------------------
__global__ __launch_bounds__(256) void kF_route(float* __restrict__ out_loss)
{
    __shared__ int ti[NPAIR];
    __shared__ float imp_s[E];
    __shared__ int disp_s[E];
    int tid = threadIdx.x, lane = tid & 31, warp = tid >> 5;
    for (int i = tid; i < NPAIR; i += 256) ti[i] = g_topi[i];
    __syncthreads();
    if (warp < E) {
        float acc = 0.f;
        for (int tok = lane; tok < NTOK; tok += 32) acc += g_probs[tok * E + warp];
        int cnt = 0;
        for (int p = lane; p < NPAIR; p += 32) cnt += (ti[p] == warp);
        acc = wred(acc); cnt = wredi(cnt);
        if (lane == 0) { imp_s[warp] = acc * (1.f / NTOK); disp_s[warp] = cnt; }
    }
    __syncthreads();
    if (tid == 0) {
        float loss = 0.f;
        for (int e = 0; e < E; e++) loss += imp_s[e] * ((float)disp_s[e] * (1.f / NTOK));
        out_loss[0] = (float)E * loss;
    }
    if (tid < E) {
        int c = 0;
        for (int p = 0; p < NPAIR; p++)
            if (ti[p] == tid) g_elist[tid * NPAIR + (c++)] = p;
        g_ecnt[tid] = c;
    }
}

// ------------------------- kG: fc1 + gelu, 6h x 6tok, pipelined -------------
#define GK_HT 192
#define GK_CH 48
#define GK_KC 16
__global__ __launch_bounds__(256) void kG_fc1(
    const float* __restrict__ w1, const float* __restrict__ b1)
{
    int h0 = blockIdx.x * GK_HT;
    int e = blockIdx.y;
    int c0 = blockIdx.z * GK_CH;
    int nt = g_ecnt[e];
    if (c0 >= nt) return;
    int ctn = min(GK_CH, nt - c0);
    __shared__ __align__(16) float ws[GK_HT * 18];
    __shared__ __align__(16) float xs[GK_CH * 18];
    __shared__ int plist[GK_CH];
    int tid = threadIdx.x;
    int hg = tid & 31, tg = tid >> 5;
    if (tid < GK_CH) plist[tid] = (tid < ctn) ? g_elist[e * NPAIR + c0 + tid] : -1;
    __syncthreads();

    int whA = tid >> 2, wdof = (tid & 3) << 2;
    const float* wbase = w1 + ((size_t)e * H + h0 + whA) * D + wdof;
    int xtok = tid >> 2, xdof = (tid & 3) << 2;
    int myp = (tid < 192) ? plist[xtok] : -1;
    const float* xbase = g_xln + ((myp >= 0) ? (size_t)(myp >> 1) * D : 0) + xdof;

    float4 pw0 = *(const float4*)wbase;
    float4 pw1 = *(const float4*)(wbase + 64 * D);
    float4 pw2 = *(const float4*)(wbase + 128 * D);
    float4 px = make_float4(0.f, 0.f, 0.f, 0.f);
    if (myp >= 0) px = *(const float4*)xbase;

    f32x2 acc[6][6];
#pragma unroll
    for (int i = 0; i < 6; i++)
#pragma unroll
        for (int j = 0; j < 6; j++) acc[i][j] = 0ull;

    for (int k0 = 0; k0 < D; k0 += GK_KC) {
        *(float2*)&ws[whA * 18 + wdof] = make_float2(pw0.x, pw0.y);
        *(float2*)&ws[whA * 18 + wdof + 2] = make_float2(pw0.z, pw0.w);
        *(float2*)&ws[(whA + 64) * 18 + wdof] = make_float2(pw1.x, pw1.y);
        *(float2*)&ws[(whA + 64) * 18 + wdof + 2] = make_float2(pw1.z, pw1.w);
        *(float2*)&ws[(whA + 128) * 18 + wdof] = make_float2(pw2.x, pw2.y);
        *(float2*)&ws[(whA + 128) * 18 + wdof + 2] = make_float2(pw2.z, pw2.w);
        if (tid < 192) {
            *(float2*)&xs[xtok * 18 + xdof] = make_float2(px.x, px.y);
            *(float2*)&xs[xtok * 18 + xdof + 2] = make_float2(px.z, px.w);
        }
        __syncthreads();
        int k1 = k0 + GK_KC;
        if (k1 < D) {
            pw0 = *(const float4*)(wbase + k1);
            pw1 = *(const float4*)(wbase + 64 * D + k1);
            pw2 = *(const float4*)(wbase + 128 * D + k1);
            if (myp >= 0) px = *(const float4*)(xbase + k1);
        }
#pragma unroll
        for (int dp = 0; dp < GK_KC / 2; dp++) {
            f32x2 wv[6], xv[6];
#pragma unroll
            for (int i = 0; i < 6; i++)
                wv[i] = *(const f32x2*)&ws[(hg + 32 * i) * 18 + 2 * dp];
#pragma unroll
            for (int j = 0; j < 6; j++)
                xv[j] = *(const f32x2*)&xs[(tg * 6 + j) * 18 + 2 * dp];
#pragma unroll
            for (int i = 0; i < 6; i++)
#pragma unroll
                for (int j = 0; j < 6; j++)
                    fma2(acc[i][j], wv[i], xv[j]);
        }
        __syncthreads();
    }
#pragma unroll
    for (int i = 0; i < 6; i++) {
        int hh = hg + 32 * i;
        float bias = b1[e * H + h0 + hh];
#pragma unroll
        for (int j = 0; j < 6; j++) {
            int tok = tg * 6 + j;
            if (tok < ctn) {
                int p = plist[tok];
                float2 u = unpk(acc[i][j]);
                g_h[(size_t)p * H + h0 + hh] = gelu_tanh(u.x + u.y + bias);
            }
        }
    }
}

// ------------------------- kH: fc2, 6d x 6tok, pipelined --------------------
__global__ __launch_bounds__(256) void kH_fc2(
    const float* __restrict__ w2, const float* __restrict__ b2)
{
    int n0 = blockIdx.x * GK_HT;
    int e = blockIdx.y;
    int c0 = blockIdx.z * GK_CH;
    int nt = g_ecnt[e];
    if (c0 >= nt) return;
    int ctn = min(GK_CH, nt - c0);
    __shared__ __align__(16) float ws[GK_HT * 18];
    __shared__ __align__(16) float xs[GK_CH * 18];
    __shared__ int plist[GK_CH];
    int tid = threadIdx.x;
    int hg = tid & 31, tg = tid >> 5;
    if (tid < GK_CH) plist[tid] = (tid < ctn) ? g_elist[e * NPAIR + c0 + tid] : -1;
    __syncthreads();

    int whA = tid >> 2, wdof = (tid & 3) << 2;
    const float* wbase = w2 + ((size_t)e * D + n0 + whA) * H + wdof;
    int xtok = tid >> 2, xdof = (tid & 3) << 2;
    int myp = (tid < 192) ? plist[xtok] : -1;
    const float* xbase = g_h + ((myp >= 0) ? (size_t)myp * H : 0) + xdof;

    float4 pw0 = *(const float4*)wbase;
    float4 pw1 = *(const float4*)(wbase + (size_t)64 * H);
    float4 pw2 = *(const float4*)(wbase + (size_t)128 * H);
    float4 px = make_float4(0.f, 0.f, 0.f, 0.f);
    if (myp >= 0) px = *(const float4*)xbase;

    f32x2 acc[6][6];
#pragma unroll
    for (int i = 0; i < 6; i++)
#pragma unroll
        for (int j = 0; j < 6; j++) acc[i][j] = 0ull;

    for (int k0 = 0; k0 < H; k0 += GK_KC) {
        *(float2*)&ws[whA * 18 + wdof] = make_float2(pw0.x, pw0.y);
        *(float2*)&ws[whA * 18 + wdof + 2] = make_float2(pw0.z, pw0.w);
        *(float2*)&ws[(whA + 64) * 18 + wdof] = make_float2(pw1.x, pw1.y);
        *(float2*)&ws[(whA + 64) * 18 + wdof + 2] = make_float2(pw1.z, pw1.w);
        *(float2*)&ws[(whA + 128) * 18 + wdof] = make_float2(pw2.x, pw2.y);
        *(float2*)&ws[(whA + 128) * 18 + wdof + 2] = make_float2(pw2.z, pw2.w);
        if (tid < 192) {
            *(float2*)&xs[xtok * 18 + xdof] = make_float2(px.x, px.y);
            *(float2*)&xs[xtok * 18 + xdof + 2] = make_float2(px.z, px.w);
        }
        __syncthreads();
        int k1 = k0 + GK_KC;
        if (k1 < H) {
            pw0 = *(const float4*)(wbase + k1);
            pw1 = *(const float4*)(wbase + (size_t)64 * H + k1);
            pw2 = *(const float4*)(wbase + (size_t)128 * H + k1);
            if (myp >= 0) px = *(const float4*)(xbase + k1);
        }
#pragma unroll
        for (int dp = 0; dp < GK_KC / 2; dp++) {
            f32x2 wv[6], xv[6];
#pragma unroll
            for (int i = 0; i < 6; i++)
                wv[i] = *(const f32x2*)&ws[(hg + 32 * i) * 18 + 2 * dp];
#pragma unroll
            for (int j = 0; j < 6; j++)
                xv[j] = *(const f32x2*)&xs[(tg * 6 + j) * 18 + 2 * dp];
#pragma unroll
            for (int i = 0; i < 6; i++)
#pragma unroll
                for (int j = 0; j < 6; j++)
                    fma2(acc[i][j], wv[i], xv[j]);
        }
        __syncthreads();
    }
#pragma unroll
    for (int i = 0; i < 6; i++) {
        int hh = hg + 32 * i;
        float bias = b2[e * D + n0 + hh];
#pragma unroll
        for (int j = 0; j < 6; j++) {
            int tok = tg * 6 + j;
            if (tok < ctn) {
                int p = plist[tok];
                float2 u = unpk(acc[i][j]);
                g_y[(size_t)p * D + n0 + hh] = u.x + u.y + bias;
            }
        }
    }
}

// ------------------------- kI: combine -------------------------------------
__global__ __launch_bounds__(256) void kI_combine(float* __restrict__ out_y)
{
    int tok = blockIdx.x;
    int tid = threadIdx.x;
    float w0 = g_topw[tok * 2], w1 = g_topw[tok * 2 + 1];
    const float* y0 = &g_y[(size_t)(tok * 2) * D];
    const float* y1 = &g_y[(size_t)(tok * 2 + 1) * D];
    for (int dd = tid; dd < D; dd += 256)
        out_y[(size_t)tok * D + dd] += w0 * y0[dd] + w1 * y1[dd];
}

// ------------------------- launch ------------------------------------------
extern "C" void kernel_launch(void* const* d_in, const int* in_sizes, int n_in,
                              void* d_out, int out_size)
{
    (void)in_sizes; (void)n_in; (void)out_size;
    const float* hidden = (const float*)d_in[0];
    const float* probe  = (const float*)d_in[1];
    const float* ipw    = (const float*)d_in[2];
    const float* ipb    = (const float*)d_in[3];
    const float* opw    = (const float*)d_in[4];
    const float* opb    = (const float*)d_in[5];
    const float* lnw    = (const float*)d_in[6];
    const float* lnb    = (const float*)d_in[7];
    const float* gw     = (const float*)d_in[8];
    const float* w1     = (const float*)d_in[9];
    const float* b1     = (const float*)d_in[10];
    const float* w2     = (const float*)d_in[11];
    const float* b2     = (const float*)d_in[12];
    float* out = (float*)d_out;

    const int OFF_LOSS = B * T * D;        // 196608
    const int OFF_AW   = OFF_LOSS + 1;     // 196609

    kA_qtilde<<<NT, 256>>>(probe, ipw, ipb);
    kB_scores<<<dim3(S / KB_ST, B), 256>>>(hidden);
    kC_softmax<<<NTOK, 384>>>(out + OFF_AW);
    kD_pooled<<<dim3(D / KD_NT, B), 256>>>(hidden);
    kE1_vproj<<<dim3(NH, B), 256>>>(ipw, ipb);
    kE2_outproj<<<dim3(6, 8), 256>>>(opw, opb, out);
    kE3_ln_gate<<<NTOK, 256>>>(lnw, lnb, gw);
    kF_route<<<1, 256>>>(out + OFF_LOSS);
    kG_fc1<<<dim3(H / GK_HT, E, 6), 256>>>(w1, b1);
    kH_fc2<<<dim3(D / GK_HT, E, 6), 256>>>(w2, b2);
    kI_combine<<<NTOK, 256>>>(out);
}

// round 6
// speedup vs baseline: 2.3658x; 1.1591x over previous
#include <cuda_runtime.h>
#include <math.h>
#include <stdint.h>

#define B 64
#define S 1024
#define D 768
#define T 4
#define E 8
#define TOPK 2
#define H 3072
#define NH 12
#define HD 64
#define NT 48          // NH*T
#define NTOK 256       // B*T
#define NPAIR 512      // NTOK*TOPK

// ---------------- packed f32x2 helpers (FFMA2: 2x fp32 throughput) ---------
// K-PACKED accumulation: lanes hold even-k / odd-k partial sums; final = lo+hi.
typedef unsigned long long f32x2;
__device__ __forceinline__ void fma2(f32x2& c, f32x2 a, f32x2 b) {
    asm("fma.rn.f32x2 %0,%1,%2,%0;" : "+l"(c) : "l"(a), "l"(b));
}
__device__ __forceinline__ float2 unpk(f32x2 v) {
    float2 r; asm("mov.b64 {%0,%1},%2;" : "=f"(r.x), "=f"(r.y) : "l"(v)); return r;
}
__device__ __forceinline__ f32x2 dup2(float v) {
    f32x2 r; asm("mov.b64 %0,{%1,%1};" : "=l"(r) : "f"(v)); return r;
}
__device__ __forceinline__ f32x2 pack2(float lo, float hi) {
    f32x2 r; asm("mov.b64 %0,{%1,%2};" : "=l"(r) : "f"(lo), "f"(hi)); return r;
}

// ---------------- cp.async helpers -----------------------------------------
__device__ __forceinline__ uint32_t sptr(const void* p) {
    return (uint32_t)__cvta_generic_to_shared(p);
}
__device__ __forceinline__ void cpa16(uint32_t dst, const void* src) {
    asm volatile("cp.async.ca.shared.global [%0], [%1], 16;" :: "r"(dst), "l"(src));
}
__device__ __forceinline__ void cpa8(uint32_t dst, const void* src) {
    asm volatile("cp.async.ca.shared.global [%0], [%1], 8;" :: "r"(dst), "l"(src));
}
__device__ __forceinline__ void cpa8z(uint32_t dst, const void* src, int sz) {
    asm volatile("cp.async.ca.shared.global [%0], [%1], 8, %2;" :: "r"(dst), "l"(src), "r"(sz));
}
#define CPCOMMIT() asm volatile("cp.async.commit_group;")
#define CPWAIT1()  asm volatile("cp.async.wait_group 1;")
#define CPWAIT0()  asm volatile("cp.async.wait_group 0;")

// ------------------------- scratch (device globals) -------------------------
__device__ __align__(16) float g_qt[NT * D];        // q-tilde [nt][d]
__device__ float g_qb[NT];
__device__ __align__(16) float g_scores[(size_t)B * NT * S];
__device__ __align__(16) float g_pooled[(size_t)B * NT * D];
__device__ __align__(16) float g_ctx[NTOK * D];
__device__ __align__(16) float g_ao[NTOK * D];
__device__ __align__(16) float g_xln[NTOK * D];
__device__ float g_probs[NTOK * E];
__device__ int   g_topi[NTOK * TOPK];
__device__ float g_topw[NTOK * TOPK];
__device__ int   g_ecnt[E];
__device__ int   g_elist[E * NPAIR];
__device__ __align__(16) float g_h[(size_t)NPAIR * H];
__device__ __align__(16) float g_y[(size_t)NPAIR * D];

__device__ __forceinline__ float wred(float v) {
#pragma unroll
    for (int o = 16; o > 0; o >>= 1) v += __shfl_down_sync(0xffffffffu, v, o);
    return v;
}
__device__ __forceinline__ float wredmax(float v) {
#pragma unroll
    for (int o = 16; o > 0; o >>= 1) v = fmaxf(v, __shfl_down_sync(0xffffffffu, v, o));
    return v;
}
__device__ __forceinline__ int wredi(int v) {
#pragma unroll
    for (int o = 16; o > 0; o >>= 1) v += __shfl_down_sync(0xffffffffu, v, o);
    return v;
}
__device__ __forceinline__ float gelu_tanh(float x) {
    return 0.5f * x * (1.f + tanhf(0.7978845608028654f * (x + 0.044715f * x * x * x)));
}

// ------------------------- kA: qtilde = (probe@Wq^T + bq) @ Wk --------------
__global__ __launch_bounds__(256) void kA_qtilde(
    const float* __restrict__ probe, const float* __restrict__ ipw,
    const float* __restrict__ ipb)
{
    int ht = blockIdx.x;
    int h = ht >> 2, t = ht & 3;
    __shared__ float q_s[HD];
    int tid = threadIdx.x, lane = tid & 31, warp = tid >> 5;

    for (int j = warp; j < HD; j += 8) {
        int row = h * HD + j;
        const float* w = ipw + (size_t)row * D;
        const float* p = probe + t * D;
        float acc = 0.f;
        for (int dd = lane; dd < D; dd += 32) acc += p[dd] * w[dd];
        acc = wred(acc);
        if (lane == 0) q_s[j] = acc + ipb[row];
    }
    __syncthreads();
    if (tid == 0) {
        float qb = 0.f;
        for (int j = 0; j < HD; j++) qb += q_s[j] * ipb[D + h * HD + j];
        g_qb[ht] = qb;
    }
    for (int dd = tid; dd < D; dd += 256) {
        float acc = 0.f;
        const float* wk = ipw + (size_t)(D + h * HD) * D + dd;
#pragma unroll 8
        for (int j = 0; j < HD; j++) acc += q_s[j] * wk[(size_t)j * D];
        g_qt[ht * D + dd] = acc;
    }
}

// ------------------------- kB: scores = hidden @ qtilde^T -------------------
// grid (8 s-tiles of 128, 64 b). 4s x 6n K-PACKED, cp.async 3-stage pipeline.
#define KB_ST 128
#define KB_KC 16
__device__ __forceinline__ void kB_load(
    int buf, int k0, const float* hb, int tid,
    uint32_t hs_s, uint32_t qs_s)
{
#pragma unroll
    for (int r = 0; r < 4; r++) {
        int idx = tid + 256 * r;
        int s = idx >> 3, c = (idx & 7) << 1;
        cpa8(hs_s + (uint32_t)((buf * KB_ST * 18 + s * 18 + c) * 4),
             hb + (size_t)s * D + k0 + c);
    }
    if (tid < 128) {
        int idx0 = tid;
        int n = idx0 >> 3, c = (idx0 & 7) << 1;
        cpa8(qs_s + (uint32_t)((buf * NT * 18 + n * 18 + c) * 4),
             g_qt + (size_t)n * D + k0 + c);
        int idx1 = tid + 128;
        n = idx1 >> 3; c = (idx1 & 7) << 1;
        cpa8(qs_s + (uint32_t)((buf * NT * 18 + n * 18 + c) * 4),
             g_qt + (size_t)n * D + k0 + c);
        int idx2 = tid + 256;
        n = idx2 >> 3; c = (idx2 & 7) << 1;
        cpa8(qs_s + (uint32_t)((buf * NT * 18 + n * 18 + c) * 4),
             g_qt + (size_t)n * D + k0 + c);
    }
    CPCOMMIT();
}
__global__ __launch_bounds__(256, 2) void kB_scores(const float* __restrict__ hidden)
{
    int b = blockIdx.y;
    int s0 = blockIdx.x * KB_ST;
    __shared__ __align__(16) float hs[3][KB_ST * 18];
    __shared__ __align__(16) float qs[3][NT * 18];
    int tid = threadIdx.x;
    int tn = tid & 7;
    int ts = tid >> 3;
    f32x2 acc[4][6];
#pragma unroll
    for (int i = 0; i < 4; i++)
#pragma unroll
        for (int j = 0; j < 6; j++) acc[i][j] = 0ull;

    const float* hb = hidden + ((size_t)b * S + s0) * D;
    uint32_t hs_s = sptr(hs), qs_s = sptr(qs);

    kB_load(0, 0, hb, tid, hs_s, qs_s);
    kB_load(1, KB_KC, hb, tid, hs_s, qs_s);

    const int NCH = D / KB_KC;   // 48
    for (int ch = 0; ch < NCH; ch++) {
        if (ch == NCH - 1) { CPWAIT0(); } else { CPWAIT1(); }
        __syncthreads();
        if (ch + 2 < NCH) kB_load((ch + 2) % 3, (ch + 2) * KB_KC, hb, tid, hs_s, qs_s);
        const float* hsb = hs[ch % 3];
        const float* qsb = qs[ch % 3];
#pragma unroll
        for (int kp = 0; kp < KB_KC / 2; kp++) {
            f32x2 hv[4], qv[6];
#pragma unroll
            for (int i = 0; i < 4; i++)
                hv[i] = *(const f32x2*)&hsb[(ts * 4 + i) * 18 + 2 * kp];
#pragma unroll
            for (int j = 0; j < 6; j++)
                qv[j] = *(const f32x2*)&qsb[(tn * 6 + j) * 18 + 2 * kp];
#pragma unroll
            for (int i = 0; i < 4; i++)
#pragma unroll
                for (int j = 0; j < 6; j++)
                    fma2(acc[i][j], hv[i], qv[j]);
        }
        __syncthreads();
    }
#pragma unroll
    for (int j = 0; j < 6; j++) {
        int n = tn * 6 + j;
        float qb = g_qb[n];
        float* row = &g_scores[((size_t)b * NT + n) * S + s0 + ts * 4];
#pragma unroll
        for (int i = 0; i < 4; i++) {
            float2 u = unpk(acc[i][j]);
            row[i] = 0.125f * (u.x + u.y + qb);
        }
    }
}

// ------------------------- kC: softmax (warp-per-head) + head-mean ----------
__global__ __launch_bounds__(384) void kC_softmax(float* __restrict__ out_aw)
{
    int bt = blockIdx.x, b = bt >> 2, t = bt & 3;
    __shared__ float stage[NH][S];
    int tid = threadIdx.x, lane = tid & 31, warp = tid >> 5;

    float* row = &g_scores[((size_t)b * NT + warp * T + t) * S];
    float4 v[8];
#pragma unroll
    for (int i = 0; i < 8; i++) v[i] = *(float4*)(row + i * 128 + lane * 4);
    float m = -1e30f;
#pragma unroll
    for (int i = 0; i < 8; i++)
        m = fmaxf(m, fmaxf(fmaxf(v[i].x, v[i].y), fmaxf(v[i].z, v[i].w)));
    m = wredmax(m);
    m = __shfl_sync(0xffffffffu, m, 0);
    float sum = 0.f;
#pragma unroll
    for (int i = 0; i < 8; i++) {
        v[i].x = __expf(v[i].x - m); v[i].y = __expf(v[i].y - m);
        v[i].z = __expf(v[i].z - m); v[i].w = __expf(v[i].w - m);
        sum += v[i].x + v[i].y + v[i].z + v[i].w;
    }
    sum = wred(sum);
    float inv = 1.f / __shfl_sync(0xffffffffu, sum, 0);
#pragma unroll
    for (int i = 0; i < 8; i++) {
        v[i].x *= inv; v[i].y *= inv; v[i].z *= inv; v[i].w *= inv;
        *(float4*)(row + i * 128 + lane * 4) = v[i];
        *(float4*)&stage[warp][i * 128 + lane * 4] = v[i];
    }
    __syncthreads();
    const float inv12 = 1.f / 12.f;
#pragma unroll
    for (int r = 0; r < 3; r++) {
        int s = tid + 384 * r;
        if (s < S) {
            float a = 0.f;
#pragma unroll
            for (int h = 0; h < NH; h++) a += stage[h][s];
            out_aw[(size_t)bt * S + s] = a * inv12;
        }
    }
}

// ------------------------- kD: pooled = attn @ hidden -----------------------
// grid (4 n-tiles of 192, 64 b). 6m x 6n K-PACKED, cp.async 3-stage pipeline.
// hidden staged [kk][n] (no transpose); k-pairs built from two LDS.32.
#define KD_NT 192
#define KD_KC 16
#define KD_HST 196
__device__ __forceinline__ void kD_load(
    int buf, int k0, int b, int n0, const float* hidden, int tid,
    uint32_t as_s, uint32_t hs_s)
{
    if (tid < 192) {
        int m = tid >> 2, c = (tid & 3) << 2;
        cpa16(as_s + (uint32_t)((buf * NT * 20 + m * 20 + c) * 4),
              g_scores + ((size_t)b * NT + m) * S + k0 + c);
    }
#pragma unroll
    for (int r = 0; r < 3; r++) {
        int idx = tid + 256 * r;
        int kk = idx & 15, cc = idx >> 4;
        cpa16(hs_s + (uint32_t)((buf * KD_KC * KD_HST + kk * KD_HST + cc * 4) * 4),
              hidden + ((size_t)b * S + k0 + kk) * D + n0 + cc * 4);
    }
    CPCOMMIT();
}
__global__ __launch_bounds__(256, 2) void kD_pooled(const float* __restrict__ hidden)
{
    int b = blockIdx.y;
    int n0 = blockIdx.x * KD_NT;
    __shared__ __align__(16) float as_[3][NT * 20];
    __shared__ __align__(16) float hsd[3][KD_KC * KD_HST];
    int tid = threadIdx.x;
    int tn = tid & 31;
    int tm = tid >> 5;
    f32x2 acc[6][6];
#pragma unroll
    for (int i = 0; i < 6; i++)
#pragma unroll
        for (int j = 0; j < 6; j++) acc[i][j] = 0ull;

    uint32_t as_s = sptr(as_), hs_s = sptr(hsd);
    kD_load(0, 0, b, n0, hidden, tid, as_s, hs_s);
    kD_load(1, KD_KC, b, n0, hidden, tid, as_s, hs_s);

    const int NCH = S / KD_KC;   // 64
    for (int ch = 0; ch < NCH; ch++) {
        if (ch == NCH - 1) { CPWAIT0(); } else { CPWAIT1(); }
        __syncthreads();
        if (ch + 2 < NCH) kD_load((ch + 2) % 3, (ch + 2) * KD_KC, b, n0, hidden, tid, as_s, hs_s);
        const float* ab = as_[ch % 3];
        const float* hb = hsd[ch % 3];
#pragma unroll
        for (int kp = 0; kp < KD_KC / 2; kp++) {
            f32x2 av[6], hv[6];
#pragma unroll
            for (int i = 0; i < 6; i++)
                av[i] = *(const f32x2*)&ab[(tm * 6 + i) * 20 + 2 * kp];
            const float* r0 = &hb[(2 * kp) * KD_HST + tn];
            const float* r1 = &hb[(2 * kp + 1) * KD_HST + tn];
#pragma unroll
            for (int j = 0; j < 6; j++)
                hv[j] = pack2(r0[32 * j], r1[32 * j]);
#pragma unroll
            for (int i = 0; i < 6; i++)
#pragma unroll
                for (int j = 0; j < 6; j++)
                    fma2(acc[i][j], av[i], hv[j]);
        }
        __syncthreads();
    }
#pragma unroll
    for (int i = 0; i < 6; i++) {
        int m = tm * 6 + i;
        float* base = &g_pooled[((size_t)b * NT + m) * D + n0];
#pragma unroll
        for (int j = 0; j < 6; j++) {
            float2 u = unpk(acc[i][j]);
            base[tn + 32 * j] = u.x + u.y;
        }
    }
}

// ------------------------- kE1: v-proj, gridded over (h, b) -----------------
__global__ __launch_bounds__(256) void kE1_vproj(
    const float* __restrict__ ipw, const float* __restrict__ ipb)
{
    int h = blockIdx.x, b = blockIdx.y;
    __shared__ float pl[T][D];
    int tid = threadIdx.x, lane = tid & 31, warp = tid >> 5;
    for (int t = 0; t < T; t++)
        for (int dd = tid; dd < D; dd += 256)
            pl[t][dd] = g_pooled[((size_t)b * NT + h * T + t) * D + dd];
    __syncthreads();
    for (int j = warp; j < HD; j += 8) {
        int row = 2 * D + h * HD + j;
        const float* w = ipw + (size_t)row * D;
        float a0 = 0.f, a1 = 0.f, a2 = 0.f, a3 = 0.f;
        for (int dd = lane; dd < D; dd += 32) {
            float wv = w[dd];
            a0 += wv * pl[0][dd]; a1 += wv * pl[1][dd];
            a2 += wv * pl[2][dd]; a3 += wv * pl[3][dd];
        }
        a0 = wred(a0); a1 = wred(a1); a2 = wred(a2); a3 = wred(a3);
        if (lane == 0) {
            float bias = ipb[row];
            g_ctx[((size_t)(b * T + 0)) * D + h * HD + j] = a0 + bias;
            g_ctx[((size_t)(b * T + 1)) * D + h * HD + j] = a1 + bias;
            g_ctx[((size_t)(b * T + 2)) * D + h * HD + j] = a2 + bias;
            g_ctx[((size_t)(b * T + 3)) * D + h * HD + j] = a3 + bias;
        }
    }
}

// ------------------------- kE2: out-proj GEMM + residual --------------------
__global__ __launch_bounds__(256) void kE2_outproj(
    const float* __restrict__ opw, const float* __restrict__ opb,
    float* __restrict__ out_y)
{
    int r0 = blockIdx.x * 128;
    int t0 = blockIdx.y * 32;
    __shared__ __align__(16) float cs[32 * 17];
    __shared__ __align__(16) float ws[16 * 132 + 16];
    int tid = threadIdx.x;
    int tr = tid & 31;
    int tt = tid >> 5;
    f32x2 acc[4][2];
#pragma unroll
    for (int t = 0; t < 4; t++) { acc[t][0] = 0ull; acc[t][1] = 0ull; }

    for (int k0 = 0; k0 < D; k0 += 16) {
#pragma unroll
        for (int r = 0; r < 2; r++) {
            int idx = tid + 256 * r;
            int tok = idx >> 4, kk = idx & 15;
            cs[tok * 17 + kk] = g_ctx[(size_t)(t0 + tok) * D + k0 + kk];
        }
#pragma unroll
        for (int r = 0; r < 2; r++) {
            int idx = tid + 256 * r;
            int rr = idx >> 2, ko = (idx & 3) << 2;
            float4 v = *(const float4*)(opw + (size_t)(r0 + rr) * D + k0 + ko);
            float* base = &ws[ko * 132 + rr + ko];
            base[0] = v.x; base[132] = v.y; base[264] = v.z; base[396] = v.w;
        }
        __syncthreads();
#pragma unroll 4
        for (int kk = 0; kk < 16; kk++) {
            ulonglong2 wu = *(const ulonglong2*)(&ws[kk * 132 + (kk & 12)] + tr * 4);
#pragma unroll
            for (int t = 0; t < 4; t++) {
                f32x2 ad = dup2(cs[(tt * 4 + t) * 17 + kk]);
                fma2(acc[t][0], wu.x, ad);
                fma2(acc[t][1], wu.y, ad);
            }
        }
        __syncthreads();
    }
    float4 bb = *(const float4*)&opb[r0 + tr * 4];
#pragma unroll
    for (int t = 0; t < 4; t++) {
        int tok = t0 + tt * 4 + t;
        float2 u0 = unpk(acc[t][0]), u1 = unpk(acc[t][1]);
        float4 o = make_float4(u0.x + bb.x, u0.y + bb.y, u1.x + bb.z, u1.y + bb.w);
        *(float4*)&out_y[(size_t)tok * D + r0 + tr * 4] = o;
        *(float4*)&g_ao[(size_t)tok * D + r0 + tr * 4] = o;
    }
}

// ------------------------- kE3: LN + gate + top2, per token -----------------
__global__ __launch_bounds__(256) void kE3_ln_gate(
    const float* __restrict__ lnw, const float* __restrict__ lnb,
    const float* __restrict__ gw)
{
    int tok = blockIdx.x;
    int t = tok & 3;
    __shared__ float x[D];
    __shared__ float red[256];
    __shared__ float lg[E];
    int tid = threadIdx.x, lane = tid & 31, warp = tid >> 5;

    float v0 = g_ao[(size_t)tok * D + tid];
    float v1 = g_ao[(size_t)tok * D + tid + 256];
    float v2 = g_ao[(size_t)tok * D + tid + 512];
    red[tid] = v0 + v1 + v2; __syncthreads();
    for (int o = 128; o > 0; o >>= 1) { if (tid < o) red[tid] += red[tid + o]; __syncthreads(); }
    float mu = red[0] * (1.f / 768.f); __syncthreads();
    float d0 = v0 - mu, d1 = v1 - mu, d2 = v2 - mu;
    red[tid] = d0 * d0 + d1 * d1 + d2 * d2; __syncthreads();
    for (int o = 128; o > 0; o >>= 1) { if (tid < o) red[tid] += red[tid + o]; __syncthreads(); }
    float rstd = rsqrtf(red[0] * (1.f / 768.f) + 1e-6f); __syncthreads();

    float x0 = d0 * rstd * lnw[tid] + lnb[tid];
    float x1 = d1 * rstd * lnw[tid + 256] + lnb[tid + 256];
    float x2 = d2 * rstd * lnw[tid + 512] + lnb[tid + 512];
    x[tid] = x0; x[tid + 256] = x1; x[tid + 512] = x2;
    g_xln[(size_t)tok * D + tid] = x0;
    g_xln[(size_t)tok * D + tid + 256] = x1;
    g_xln[(size_t)tok * D + tid + 512] = x2;
    __syncthreads();

    if (warp < E) {
        float acc = 0.f;
        for (int dd = lane; dd < D; dd += 32)
            acc += x[dd] * gw[((size_t)t * D + dd) * E + warp];
        acc = wred(acc);
        if (lane == 0) lg[warp] = acc;
    }
    __syncthreads();
    if (tid == 0) {
        float p[E];
        float mx = lg[0];
        for (int e = 1; e < E; e++) mx = fmaxf(mx, lg[e]);
        float sum = 0.f;
        for (int e = 0; e < E; e++) { p[e] = __expf(lg[e] - mx); sum += p[e]; }
        float inv = 1.f / sum;
        for (int e = 0; e < E; e++) { p[e] *= inv; g_probs[tok * E + e] = p[e]; }
        int i0 = 0;
        for (int e = 1; e < E; e++) if (p[e] > p[i0]) i0 = e;
        int i1 = (i0 == 0) ? 1 : 0;
        for (int e = 0; e < E; e++) if (e != i0 && p[e] > p[i1]) i1 = e;
        float inv2 = 1.f / (p[i0] + p[i1]);
        g_topi[tok * 2] = i0; g_topi[tok * 2 + 1] = i1;
        g_topw[tok * 2] = p[i0] * inv2; g_topw[tok * 2 + 1] = p[i1] * inv2;
    }
}

// ------------------------- kF: routing lists + moe_loss ---------------------
__global__ __launch_bounds__(256) void kF_route(float* __restrict__ out_loss)
{
    __shared__ int ti[NPAIR];
    __shared__ float imp_s[E];
    __shared__ int disp_s[E];
    int tid = threadIdx.x, lane = tid & 31, warp = tid >> 5;
    for (int i = tid; i < NPAIR; i += 256) ti[i] = g_topi[i];
    __syncthreads();
    if (warp < E) {
        float acc = 0.f;
        for (int tok = lane; tok < NTOK; tok += 32) acc += g_probs[tok * E + warp];
        int cnt = 0;
        for (int p = lane; p < NPAIR; p += 32) cnt += (ti[p] == warp);
        acc = wred(acc); cnt = wredi(cnt);
        if (lane == 0) { imp_s[warp] = acc * (1.f / NTOK); disp_s[warp] = cnt; }
    }
    __syncthreads();
    if (tid == 0) {
        float loss = 0.f;
        for (int e = 0; e < E; e++) loss += imp_s[e] * ((float)disp_s[e] * (1.f / NTOK));
        out_loss[0] = (float)E * loss;
    }
    if (tid < E) {
        int c = 0;
        for (int p = 0; p < NPAIR; p++)
            if (ti[p] == tid) g_elist[tid * NPAIR + (c++)] = p;
        g_ecnt[tid] = c;
    }
}

// ------------------------- kG/kH common: 6out x 6tok, cp.async pipeline -----
#define GK_HT 192
#define GK_CH 48
#define GK_KC 16
__device__ __forceinline__ void gk_load(
    int buf, int k0, const float* wbase0, size_t wstride,
    const float* xsrc, size_t xstride, const int* plist, int pshift,
    int tid, uint32_t ws_s, uint32_t xs_s)
{
#pragma unroll
    for (int r = 0; r < 6; r++) {
        int idx = tid + 256 * r;
        int hh = idx >> 3, c = (idx & 7) << 1;
        cpa8(ws_s + (uint32_t)((buf * GK_HT * 18 + hh * 18 + c) * 4),
             wbase0 + (size_t)hh * wstride + k0 + c);
    }
    if (tid < 128) {
#pragma unroll
        for (int r = 0; r < 3; r++) {
            int idx = tid + 128 * r;
            int tok = idx >> 3, c = (idx & 7) << 1;
            int p = plist[tok];
            const float* src = xsrc + ((p >= 0) ? (size_t)(p >> pshift) * xstride : 0) + k0 + c;
            cpa8z(xs_s + (uint32_t)((buf * GK_CH * 18 + tok * 18 + c) * 4),
                  src, (p >= 0) ? 8 : 0);
        }
    }
    CPCOMMIT();
}

// ------------------------- kG: fc1 + gelu ------------------------------------
__global__ __launch_bounds__(256, 2) void kG_fc1(
    const float* __restrict__ w1, const float* __restrict__ b1)
{
    int h0 = blockIdx.x * GK_HT;
    int e = blockIdx.y;
    int c0 = blockIdx.z * GK_CH;
    int nt = g_ecnt[e];
    if (c0 >= nt) return;
    int ctn = min(GK_CH, nt - c0);
    __shared__ __align__(16) float ws[3][GK_HT * 18];
    __shared__ __align__(16) float xs[3][GK_CH * 18];
    __shared__ int plist[GK_CH];
    int tid = threadIdx.x;
    int hg = tid & 31, tg = tid >> 5;
    if (tid < GK_CH) plist[tid] = (tid < ctn) ? g_elist[e * NPAIR + c0 + tid] : -1;
    __syncthreads();

    const float* wbase0 = w1 + (size_t)e * H * D + (size_t)h0 * D;
    uint32_t ws_s = sptr(ws), xs_s = sptr(xs);
    gk_load(0, 0, wbase0, D, g_xln, D, plist, 1, tid, ws_s, xs_s);
    gk_load(1, GK_KC, wbase0, D, g_xln, D, plist, 1, tid, ws_s, xs_s);

    f32x2 acc[6][6];
#pragma unroll
    for (int i = 0; i < 6; i++)
#pragma unroll
        for (int j = 0; j < 6; j++) acc[i][j] = 0ull;

    const int NCH = D / GK_KC;   // 48
    for (int ch = 0; ch < NCH; ch++) {
        if (ch == NCH - 1) { CPWAIT0(); } else { CPWAIT1(); }
        __syncthreads();
        if (ch + 2 < NCH) gk_load((ch + 2) % 3, (ch + 2) * GK_KC, wbase0, D, g_xln, D, plist, 1, tid, ws_s, xs_s);
        const float* wsb = ws[ch % 3];
        const float* xsb = xs[ch % 3];
#pragma unroll
        for (int dp = 0; dp < GK_KC / 2; dp++) {
            f32x2 wv[6], xv[6];
#pragma unroll
            for (int i = 0; i < 6; i++)
                wv[i] = *(const f32x2*)&wsb[(hg + 32 * i) * 18 + 2 * dp];
#pragma unroll
            for (int j = 0; j < 6; j++)
                xv[j] = *(const f32x2*)&xsb[(tg * 6 + j) * 18 + 2 * dp];
#pragma unroll
            for (int i = 0; i < 6; i++)
#pragma unroll
                for (int j = 0; j < 6; j++)
                    fma2(acc[i][j], wv[i], xv[j]);
        }
        __syncthreads();
    }
#pragma unroll
    for (int i = 0; i < 6; i++) {
        int hh = hg + 32 * i;
        float bias = b1[e * H + h0 + hh];
#pragma unroll
        for (int j = 0; j < 6; j++) {
            int tok = tg * 6 + j;
            if (tok < ctn) {
                int p = plist[tok];
                float2 u = unpk(acc[i][j]);
                g_h[(size_t)p * H + h0 + hh] = gelu_tanh(u.x + u.y + bias);
            }
        }
    }
}

// ------------------------- kH: fc2 ------------------------------------------
__global__ __launch_bounds__(256, 2) void kH_fc2(
    const float* __restrict__ w2, const float* __restrict__ b2)
{
    int n0 = blockIdx.x * GK_HT;
    int e = blockIdx.y;
    int c0 = blockIdx.z * GK_CH;
    int nt = g_ecnt[e];
    if (c0 >= nt) return;
    int ctn = min(GK_CH, nt - c0);
    __shared__ __align__(16) float ws[3][GK_HT * 18];
    __shared__ __align__(16) float xs[3][GK_CH * 18];
    __shared__ int plist[GK_CH];
    int tid = threadIdx.x;
    int hg = tid & 31, tg = tid >> 5;
    if (tid < GK_CH) plist[tid] = (tid < ctn) ? g_elist[e * NPAIR + c0 + tid] : -1;
    __syncthreads();

    const float* wbase0 = w2 + (size_t)e * D * H + (size_t)n0 * H;
    uint32_t ws_s = sptr(ws), xs_s = sptr(xs);
    gk_load(0, 0, wbase0, H, g_h, H, plist, 0, tid, ws_s, xs_s);
    gk_load(1, GK_KC, wbase0, H, g_h, H, plist, 0, tid, ws_s, xs_s);

    f32x2 acc[6][6];
#pragma unroll
    for (int i = 0; i < 6; i++)
#pragma unroll
        for (int j = 0; j < 6; j++) acc[i][j] = 0ull;

    const int NCH = H / GK_KC;   // 192
    for (int ch = 0; ch < NCH; ch++) {
        if (ch == NCH - 1) { CPWAIT0(); } else { CPWAIT1(); }
        __syncthreads();
        if (ch + 2 < NCH) gk_load((ch + 2) % 3, (ch + 2) * GK_KC, wbase0, H, g_h, H, plist, 0, tid, ws_s, xs_s);
        const float* wsb = ws[ch % 3];
        const float* xsb = xs[ch % 3];
#pragma unroll
        for (int dp = 0; dp < GK_KC / 2; dp++) {
            f32x2 wv[6], xv[6];
#pragma unroll
            for (int i = 0; i < 6; i++)
                wv[i] = *(const f32x2*)&wsb[(hg + 32 * i) * 18 + 2 * dp];
#pragma unroll
            for (int j = 0; j < 6; j++)
                xv[j] = *(const f32x2*)&xsb[(tg * 6 + j) * 18 + 2 * dp];
#pragma unroll
            for (int i = 0; i < 6; i++)
#pragma unroll
                for (int j = 0; j < 6; j++)
                    fma2(acc[i][j], wv[i], xv[j]);
        }
        __syncthreads();
    }
#pragma unroll
    for (int i = 0; i < 6; i++) {
        int hh = hg + 32 * i;
        float bias = b2[e * D + n0 + hh];
#pragma unroll
        for (int j = 0; j < 6; j++) {
            int tok = tg * 6 + j;
            if (tok < ctn) {
                int p = plist[tok];
                float2 u = unpk(acc[i][j]);
                g_y[(size_t)p * D + n0 + hh] = u.x + u.y + bias;
            }
        }
    }
}

// ------------------------- kI: combine -------------------------------------
__global__ __launch_bounds__(256) void kI_combine(float* __restrict__ out_y)
{
    int tok = blockIdx.x;
    int tid = threadIdx.x;
    float w0 = g_topw[tok * 2], w1 = g_topw[tok * 2 + 1];
    const float* y0 = &g_y[(size_t)(tok * 2) * D];
    const float* y1 = &g_y[(size_t)(tok * 2 + 1) * D];
    for (int dd = tid; dd < D; dd += 256)
        out_y[(size_t)tok * D + dd] += w0 * y0[dd] + w1 * y1[dd];
}

// ------------------------- launch ------------------------------------------
extern "C" void kernel_launch(void* const* d_in, const int* in_sizes, int n_in,
                              void* d_out, int out_size)
{
    (void)in_sizes; (void)n_in; (void)out_size;
    const float* hidden = (const float*)d_in[0];
    const float* probe  = (const float*)d_in[1];
    const float* ipw    = (const float*)d_in[2];
    const float* ipb    = (const float*)d_in[3];
    const float* opw    = (const float*)d_in[4];
    const float* opb    = (const float*)d_in[5];
    const float* lnw    = (const float*)d_in[6];
    const float* lnb    = (const float*)d_in[7];
    const float* gw     = (const float*)d_in[8];
    const float* w1     = (const float*)d_in[9];
    const float* b1     = (const float*)d_in[10];
    const float* w2     = (const float*)d_in[11];
    const float* b2     = (const float*)d_in[12];
    float* out = (float*)d_out;

    const int OFF_LOSS = B * T * D;        // 196608
    const int OFF_AW   = OFF_LOSS + 1;     // 196609

    kA_qtilde<<<NT, 256>>>(probe, ipw, ipb);
    kB_scores<<<dim3(S / KB_ST, B), 256>>>(hidden);
    kC_softmax<<<NTOK, 384>>>(out + OFF_AW);
    kD_pooled<<<dim3(D / KD_NT, B), 256>>>(hidden);
    kE1_vproj<<<dim3(NH, B), 256>>>(ipw, ipb);
    kE2_outproj<<<dim3(6, 8), 256>>>(opw, opb, out);
    kE3_ln_gate<<<NTOK, 256>>>(lnw, lnb, gw);
    kF_route<<<1, 256>>>(out + OFF_LOSS);
    kG_fc1<<<dim3(H / GK_HT, E, 11), 256>>>(w1, b1);
    kH_fc2<<<dim3(D / GK_HT, E, 11), 256>>>(w2, b2);
    kI_combine<<<NTOK, 256>>>(out);
}